// round 11
// baseline (speedup 1.0000x reference)
#include <cuda_runtime.h>
#include <cuda_bf16.h>
#include <cstdint>

#define NN 20000
#define NE 320000

// ---------------- single aligned device scratch ------------------------------
#define OFF_CNT 0
#define SZ_CNT  20480
#define OFF_AGG (OFF_CNT + SZ_CNT)
#define SZ_AGG  (NN * 512)
#define OFF_H1  (OFF_AGG + SZ_AGG)
#define SZ_H1   (NN * 512)
#define OFF_H2  (OFF_H1 + SZ_H1)
#define SZ_H2   (NN * 512)
#define OFF_H3  (OFF_H2 + SZ_H2)
#define SZ_H3   (NN * 1024)
#define OFF_W1L (OFF_H3 + SZ_H3)
#define OFF_W1R (OFF_W1L + 512*256)
#define OFF_W2L (OFF_W1R + 512*256)
#define OFF_W2R (OFF_W2L + 512*512)
#define OFF_W3L (OFF_W2R + 512*512)
#define OFF_W3R (OFF_W3L + 1024*512)
#define OFF_WFC (OFF_W3R + 1024*512)
#define OFF_XC  (OFF_WFC + 512*1024)
#define OFF_RP   (OFF_XC + NN*256)
#define OFF_FILL (OFF_RP + 20512)
#define OFF_CSR  (OFF_FILL + 20480)
#define SZ_TOTAL (OFF_CSR + NE)

__device__ __align__(128) float g_scratch[SZ_TOTAL];

__device__ __forceinline__ float* bufp(int off, const float* ext) {
    return (off >= 0) ? (g_scratch + off) : const_cast<float*>(ext);
}
__device__ __forceinline__ float f2tf(float f) {
    uint32_t r;
    asm("cvt.rna.tf32.f32 %0, %1;" : "=r"(r) : "f"(f));
    return __uint_as_float(r);
}
__device__ __forceinline__ uint32_t smem_u32(const void* p) {
    uint32_t a;
    asm("{ .reg .u64 t; cvta.to.shared.u64 t, %1; cvt.u32.u64 %0, t; }" : "=r"(a) : "l"(p));
    return a;
}

// ---------------- dual-region zero ---------------------------------------------
__global__ void zero2_kernel(int offA, int n4A, int offB, int n4B) {
    int i = blockIdx.x * blockDim.x + threadIdx.x;
    int stride = gridDim.x * blockDim.x;
    float4 z = make_float4(0.f, 0.f, 0.f, 0.f);
    float4* pa = (float4*)(g_scratch + offA);
    float4* pb = (float4*)(g_scratch + offB);
    for (int j = i; j < n4A; j += stride) pa[j] = z;
    for (int j = i; j < n4B; j += stride) pb[j] = z;
}

// ---------------- degree count (int) -------------------------------------------
__global__ void count_kernel(const int* __restrict__ ei, int E) {
    int* cnt = (int*)(g_scratch + OFF_CNT);
    int i = blockIdx.x * blockDim.x + threadIdx.x;
    int stride = gridDim.x * blockDim.x;
    for (; i < E; i += stride) atomicAdd(&cnt[ei[E + i]], 1);
}

// ---------------- prefix sum over counts -> row_ptr ----------------------------
__global__ void prefix_kernel() {
    __shared__ int sh[1024];
    __shared__ int carry;
    const int tid = threadIdx.x;
    int* rp = (int*)(g_scratch + OFF_RP);
    const int* cnt = (const int*)(g_scratch + OFF_CNT);
    if (tid == 0) { carry = 0; rp[0] = 0; }
    __syncthreads();
    for (int base = 0; base < NN; base += 1024) {
        int i = base + tid;
        int v = (i < NN) ? cnt[i] : 0;
        sh[tid] = v;
        __syncthreads();
        for (int off = 1; off < 1024; off <<= 1) {
            int t = (tid >= off) ? sh[tid - off] : 0;
            __syncthreads();
            sh[tid] += t;
            __syncthreads();
        }
        if (i < NN) rp[i + 1] = carry + sh[tid];
        __syncthreads();
        if (tid == 0) carry += sh[1023];
        __syncthreads();
    }
}

// ---------------- fill CSR ------------------------------------------------------
__global__ void fillcsr_kernel(const int* __restrict__ ei, int E) {
    const int* rp = (const int*)(g_scratch + OFF_RP);
    int* fill = (int*)(g_scratch + OFF_FILL);
    int* csr = (int*)(g_scratch + OFF_CSR);
    int i = blockIdx.x * blockDim.x + threadIdx.x;
    int stride = gridDim.x * blockDim.x;
    for (; i < E; i += stride) {
        int s = ei[i];
        int t = ei[E + i];
        int pos = rp[t] + atomicAdd(&fill[t], 1);
        csr[pos] = s;
    }
}

// ---------------- gather-mean (warp per node) -----------------------------------
__global__ void gather_kernel(int xoff, const float* __restrict__ xext, int d) {
    const float* x = bufp(xoff, xext);
    float* agg = g_scratch + OFF_AGG;
    const int* rp = (const int*)(g_scratch + OFF_RP);
    const int* csr = (const int*)(g_scratch + OFF_CSR);
    int node = (blockIdx.x * blockDim.x + threadIdx.x) >> 5;
    int lane = threadIdx.x & 31;
    if (node >= NN) return;
    int beg = rp[node], end = rp[node + 1];
    const int nv = d >> 7;

    float4 acc[4];
#pragma unroll
    for (int v = 0; v < 4; v++) acc[v] = make_float4(0.f, 0.f, 0.f, 0.f);

    int e = beg;
    for (; e + 1 < end; e += 2) {
        const float* x0 = x + (size_t)csr[e] * d;
        const float* x1 = x + (size_t)csr[e + 1] * d;
#pragma unroll 4
        for (int v = 0; v < nv; v++) {
            float4 a = *(const float4*)(x0 + lane * 4 + v * 128);
            float4 b = *(const float4*)(x1 + lane * 4 + v * 128);
            acc[v].x += a.x + b.x; acc[v].y += a.y + b.y;
            acc[v].z += a.z + b.z; acc[v].w += a.w + b.w;
        }
    }
    if (e < end) {
        const float* x0 = x + (size_t)csr[e] * d;
#pragma unroll 4
        for (int v = 0; v < nv; v++) {
            float4 a = *(const float4*)(x0 + lane * 4 + v * 128);
            acc[v].x += a.x; acc[v].y += a.y; acc[v].z += a.z; acc[v].w += a.w;
        }
    }
    float sc = 1.0f / (float)max(end - beg, 1);
    float* out = agg + (size_t)node * d + lane * 4;
#pragma unroll 4
    for (int v = 0; v < nv; v++) {
        float4 o;
        o.x = f2tf(acc[v].x * sc); o.y = f2tf(acc[v].y * sc);
        o.z = f2tf(acc[v].z * sc); o.w = f2tf(acc[v].w * sc);
        *(float4*)(out + v * 128) = o;
    }
}

// ---------------- merged weight transpose (+tf32) -------------------------------
__global__ void transall_kernel(const float* __restrict__ W1l, const float* __restrict__ W1r,
                                const float* __restrict__ W2l, const float* __restrict__ W2r,
                                const float* __restrict__ W3l, const float* __restrict__ W3r,
                                const float* __restrict__ Wfc) {
    __shared__ float t[32][33];
    int b = blockIdx.x;
    const float* src; int dstOff, K, N, lt;
    if      (b < 128)  { src = W1l; dstOff = OFF_W1L; K = 256;  N = 512;  lt = b; }
    else if (b < 256)  { src = W1r; dstOff = OFF_W1R; K = 256;  N = 512;  lt = b - 128; }
    else if (b < 512)  { src = W2l; dstOff = OFF_W2L; K = 512;  N = 512;  lt = b - 256; }
    else if (b < 768)  { src = W2r; dstOff = OFF_W2R; K = 512;  N = 512;  lt = b - 512; }
    else if (b < 1280) { src = W3l; dstOff = OFF_W3L; K = 512;  N = 1024; lt = b - 768; }
    else if (b < 1792) { src = W3r; dstOff = OFF_W3R; K = 512;  N = 1024; lt = b - 1280; }
    else               { src = Wfc; dstOff = OFF_WFC; K = 1024; N = 512;  lt = b - 1792; }
    int ntx = N >> 5;
    int nb = (lt % ntx) * 32, kb = (lt / ntx) * 32;
    int tx = threadIdx.x, ty = threadIdx.y;
    for (int i = ty; i < 32; i += 8)
        t[i][tx] = src[(size_t)(kb + i) * N + nb + tx];
    __syncthreads();
    float* dst = g_scratch + dstOff;
    for (int i = ty; i < 32; i += 8)
        dst[(size_t)(nb + i) * K + kb + tx] = f2tf(t[tx][i]);
}

// ---------------- tf32-round copy ------------------------------------------------
__global__ void cvt_kernel(const float* __restrict__ src, int dstOff, int n4) {
    float4* dst = (float4*)(g_scratch + dstOff);
    int i = blockIdx.x * blockDim.x + threadIdx.x;
    int stride = gridDim.x * blockDim.x;
    for (; i < n4; i += stride) {
        float4 v = ((const float4*)src)[i];
        v.x = f2tf(v.x); v.y = f2tf(v.y); v.z = f2tf(v.z); v.w = f2tf(v.w);
        dst[i] = v;
    }
}

// ---------------- tf32 mma.sync GEMM, 4-stage cp.async, PERSISTENT tiles -------
// CTA tile 128x128, 256 threads = 8 warps (2 M x 4 N), warp tile 64x32, BK=16.
#define BM 128
#define BN 128
#define BKC 16
#define PADR 20
#define NSTG 4
#define STG_F (BM * PADR)
#define SMEM_GEMM (NSTG * STG_F * 2 * 4)
#define NPERS 296   /* 148 SMs x 2 CTAs */

__global__ __launch_bounds__(256)
void gemm_mma(int a1off, const float* a1ext, int a2off, const float* a2ext, int hasA2,
              int b1off, int b2off, const float* __restrict__ bias,
              int coff, float* cext, int M, int N, int K, int doRelu, int doRound,
              int ntx, int ntiles) {
    extern __shared__ float sm[];
    float* sA = sm;
    float* sB = sm + NSTG * STG_F;

    const float* A1 = bufp(a1off, a1ext);
    const float* A2 = bufp(a2off, a2ext);
    const float* B1 = g_scratch + b1off;
    const float* B2 = g_scratch + b2off;
    float* C = bufp(coff, cext);

    const int tid = threadIdx.x, wid = tid >> 5, lane = tid & 31;
    const int wm = (wid >> 2) * 64;
    const int wn = (wid & 3) * 32;
    const int lr = tid >> 2;
    const int lc4 = (tid & 3) * 4;
    const int qrow = lane >> 2;
    const int qcol = lane & 3;

    const uint32_t sAu = smem_u32(sA);
    const uint32_t sBu = smem_u32(sB);

    const int Ktot = hasA2 ? 2 * K : K;
    const int nch = Ktot / BKC;

    for (int t = blockIdx.x; t < ntiles; t += gridDim.x) {
        const int rowBase = (t / ntx) * BM;
        const int colBase = (t % ntx) * BN;

        float acc[4][4][4];
#pragma unroll
        for (int mi = 0; mi < 4; mi++)
#pragma unroll
            for (int ni = 0; ni < 4; ni++)
#pragma unroll
                for (int r = 0; r < 4; r++) acc[mi][ni][r] = 0.f;

        auto load_stage = [&](int c) {
            int stg = c & (NSTG - 1);
            int k0 = c * BKC;
            const float* A; const float* B; int kk;
            if (k0 < K) { A = A1; B = B1; kk = k0; }
            else        { A = A2; B = B2; kk = k0 - K; }
#pragma unroll
            for (int p = 0; p < 2; p++) {
                int row = lr + p * 64;
                int gm = rowBase + row;
                const float* src = A + (size_t)gm * K + kk + lc4;
                uint32_t dst = sAu + (uint32_t)(stg * STG_F + row * PADR + lc4) * 4u;
                uint32_t sz = (gm < M) ? 16u : 0u;
                asm volatile("cp.async.cg.shared.global [%0], [%1], 16, %2;"
                             :: "r"(dst), "l"(src), "r"(sz));
            }
#pragma unroll
            for (int p = 0; p < 2; p++) {
                int row = lr + p * 64;
                const float* src = B + (size_t)(colBase + row) * K + kk + lc4;
                uint32_t dst = sBu + (uint32_t)(stg * STG_F + row * PADR + lc4) * 4u;
                asm volatile("cp.async.cg.shared.global [%0], [%1], 16, %2;"
                             :: "r"(dst), "l"(src), "r"(16u));
            }
        };

#pragma unroll
        for (int i = 0; i < NSTG - 1; i++) {
            if (i < nch) load_stage(i);
            asm volatile("cp.async.commit_group;" ::: "memory");
        }

        for (int ch = 0; ch < nch; ch++) {
            asm volatile("cp.async.wait_group 2;" ::: "memory");
            __syncthreads();

            int pre = ch + NSTG - 1;
            if (pre < nch) load_stage(pre);
            asm volatile("cp.async.commit_group;" ::: "memory");

            const float* As = sA + (ch & (NSTG - 1)) * STG_F;
            const float* Bs = sB + (ch & (NSTG - 1)) * STG_F;
#pragma unroll
            for (int ks = 0; ks < 2; ks++) {
                const int kof = ks * 8;
                uint32_t af[4][4], bf[4][2];
#pragma unroll
                for (int mi = 0; mi < 4; mi++) {
                    int r0 = wm + mi * 16 + qrow;
                    int c0 = kof + qcol;
                    af[mi][0] = __float_as_uint(As[r0 * PADR + c0]);
                    af[mi][1] = __float_as_uint(As[(r0 + 8) * PADR + c0]);
                    af[mi][2] = __float_as_uint(As[r0 * PADR + c0 + 4]);
                    af[mi][3] = __float_as_uint(As[(r0 + 8) * PADR + c0 + 4]);
                }
#pragma unroll
                for (int ni = 0; ni < 4; ni++) {
                    int cn = wn + ni * 8 + qrow;
                    int rk = kof + qcol;
                    bf[ni][0] = __float_as_uint(Bs[cn * PADR + rk]);
                    bf[ni][1] = __float_as_uint(Bs[cn * PADR + rk + 4]);
                }
#pragma unroll
                for (int mi = 0; mi < 4; mi++)
#pragma unroll
                    for (int ni = 0; ni < 4; ni++) {
                        asm volatile(
                            "mma.sync.aligned.m16n8k8.row.col.f32.tf32.tf32.f32 "
                            "{%0,%1,%2,%3}, {%4,%5,%6,%7}, {%8,%9}, {%0,%1,%2,%3};"
                            : "+f"(acc[mi][ni][0]), "+f"(acc[mi][ni][1]),
                              "+f"(acc[mi][ni][2]), "+f"(acc[mi][ni][3])
                            : "r"(af[mi][0]), "r"(af[mi][1]), "r"(af[mi][2]), "r"(af[mi][3]),
                              "r"(bf[ni][0]), "r"(bf[ni][1]));
                    }
            }
        }

        // epilogue
#pragma unroll
        for (int mi = 0; mi < 4; mi++) {
            int gm0 = rowBase + wm + mi * 16 + qrow;
            int gm1 = gm0 + 8;
#pragma unroll
            for (int ni = 0; ni < 4; ni++) {
                int col = colBase + wn + ni * 8 + 2 * qcol;
                float2 bv = *(const float2*)(bias + col);
                float r0 = acc[mi][ni][0] + bv.x;
                float r1 = acc[mi][ni][1] + bv.y;
                float r2 = acc[mi][ni][2] + bv.x;
                float r3 = acc[mi][ni][3] + bv.y;
                if (doRelu) {
                    r0 = fmaxf(r0, 0.f); r1 = fmaxf(r1, 0.f);
                    r2 = fmaxf(r2, 0.f); r3 = fmaxf(r3, 0.f);
                }
                if (doRound) {
                    r0 = f2tf(r0); r1 = f2tf(r1); r2 = f2tf(r2); r3 = f2tf(r3);
                }
                if (gm0 < M) *(float2*)(C + (size_t)gm0 * N + col) = make_float2(r0, r1);
                if (gm1 < M) *(float2*)(C + (size_t)gm1 * N + col) = make_float2(r2, r3);
            }
        }
        // guard stage-smem reuse across tile boundary
        __syncthreads();
    }
}

// ---------------- launch --------------------------------------------------------
extern "C" void kernel_launch(void* const* d_in, const int* in_sizes, int n_in,
                              void* d_out, int out_size) {
    const float* x   = (const float*)d_in[0];
    const int*   ei  = (const int*)d_in[1];
    const float* Wl1 = (const float*)d_in[2];
    const float* bl1 = (const float*)d_in[3];
    const float* Wr1 = (const float*)d_in[4];
    const float* Wl2 = (const float*)d_in[5];
    const float* bl2 = (const float*)d_in[6];
    const float* Wr2 = (const float*)d_in[7];
    const float* Wl3 = (const float*)d_in[8];
    const float* bl3 = (const float*)d_in[9];
    const float* Wr3 = (const float*)d_in[10];
    const float* Wfc = (const float*)d_in[11];
    const float* bfc = (const float*)d_in[12];
    float* out = (float*)d_out;

    cudaFuncSetAttribute(gemm_mma, cudaFuncAttributeMaxDynamicSharedMemorySize, SMEM_GEMM);

    const int M = NN, E = NE;
    dim3 tb(32, 8);

    transall_kernel<<<2304, tb>>>(Wl1, Wr1, Wl2, Wr2, Wl3, Wr3, Wfc);
    cvt_kernel<<<1250, 256>>>(x, OFF_XC, NN * 256 / 4);

    zero2_kernel<<<40, 256>>>(OFF_CNT, SZ_CNT / 4, OFF_FILL, 20480 / 4);
    count_kernel<<<1250, 256>>>(ei, E);
    prefix_kernel<<<1, 1024>>>();
    fillcsr_kernel<<<1250, 256>>>(ei, E);

    const int gatherBlocks = (NN * 32 + 255) / 256;
    const int gy = (M + BM - 1) / BM;   // 157

    // ---- layer 1: 256 -> 512  (ntx=4, ntiles=628)
    gather_kernel<<<gatherBlocks, 256>>>(-1, x, 256);
    gemm_mma<<<NPERS, 256, SMEM_GEMM>>>(
        OFF_AGG, nullptr, OFF_XC, nullptr, 1, OFF_W1L, OFF_W1R, bl1,
        OFF_H1, nullptr, M, 512, 256, 1, 1, 512 / BN, (512 / BN) * gy);

    // ---- layer 2: 512 -> 512
    gather_kernel<<<gatherBlocks, 256>>>(OFF_H1, nullptr, 512);
    gemm_mma<<<NPERS, 256, SMEM_GEMM>>>(
        OFF_AGG, nullptr, OFF_H1, nullptr, 1, OFF_W2L, OFF_W2R, bl2,
        OFF_H2, nullptr, M, 512, 512, 1, 1, 512 / BN, (512 / BN) * gy);

    // ---- layer 3: 512 -> 1024 (ntx=8, ntiles=1256)
    gather_kernel<<<gatherBlocks, 256>>>(OFF_H2, nullptr, 512);
    gemm_mma<<<NPERS, 256, SMEM_GEMM>>>(
        OFF_AGG, nullptr, OFF_H2, nullptr, 1, OFF_W3L, OFF_W3R, bl3,
        OFF_H3, nullptr, M, 1024, 512, 1, 1, 1024 / BN, (1024 / BN) * gy);

    // ---- final FC: 1024 -> 512
    gemm_mma<<<NPERS, 256, SMEM_GEMM>>>(
        OFF_H3, nullptr, -1, nullptr, 0, OFF_WFC, OFF_WFC, bfc,
        -1, out, M, 512, 1024, 0, 0, 512 / BN, (512 / BN) * gy);
}

// round 12
// speedup vs baseline: 1.0207x; 1.0207x over previous
#include <cuda_runtime.h>
#include <cuda_bf16.h>
#include <cstdint>

#define NN 20000
#define NE 320000

// ---------------- single aligned device scratch ------------------------------
#define OFF_CNT 0
#define SZ_CNT  20480
#define OFF_AGG (OFF_CNT + SZ_CNT)
#define SZ_AGG  (NN * 512)
#define OFF_H1  (OFF_AGG + SZ_AGG)
#define SZ_H1   (NN * 512)
#define OFF_H2  (OFF_H1 + SZ_H1)
#define SZ_H2   (NN * 512)
#define OFF_H3  (OFF_H2 + SZ_H2)
#define SZ_H3   (NN * 1024)
#define OFF_W1L (OFF_H3 + SZ_H3)
#define OFF_W1R (OFF_W1L + 512*256)
#define OFF_W2L (OFF_W1R + 512*256)
#define OFF_W2R (OFF_W2L + 512*512)
#define OFF_W3L (OFF_W2R + 512*512)
#define OFF_W3R (OFF_W3L + 1024*512)
#define OFF_WFC (OFF_W3R + 1024*512)
#define OFF_XC  (OFF_WFC + 512*1024)
#define OFF_RP   (OFF_XC + NN*256)
#define OFF_FILL (OFF_RP + 20512)
#define OFF_CSR  (OFF_FILL + 20480)
#define SZ_TOTAL (OFF_CSR + NE)

__device__ __align__(128) float g_scratch[SZ_TOTAL];

__device__ __forceinline__ float* bufp(int off, const float* ext) {
    return (off >= 0) ? (g_scratch + off) : const_cast<float*>(ext);
}
__device__ __forceinline__ float f2tf(float f) {
    uint32_t r;
    asm("cvt.rna.tf32.f32 %0, %1;" : "=r"(r) : "f"(f));
    return __uint_as_float(r);
}
__device__ __forceinline__ uint32_t smem_u32(const void* p) {
    uint32_t a;
    asm("{ .reg .u64 t; cvta.to.shared.u64 t, %1; cvt.u32.u64 %0, t; }" : "=r"(a) : "l"(p));
    return a;
}

// ---------------- dual-region zero ---------------------------------------------
__global__ void zero2_kernel(int offA, int n4A, int offB, int n4B) {
    int i = blockIdx.x * blockDim.x + threadIdx.x;
    int stride = gridDim.x * blockDim.x;
    float4 z = make_float4(0.f, 0.f, 0.f, 0.f);
    float4* pa = (float4*)(g_scratch + offA);
    float4* pb = (float4*)(g_scratch + offB);
    for (int j = i; j < n4A; j += stride) pa[j] = z;
    for (int j = i; j < n4B; j += stride) pb[j] = z;
}

// ---------------- degree count (int) -------------------------------------------
__global__ void count_kernel(const int* __restrict__ ei, int E) {
    int* cnt = (int*)(g_scratch + OFF_CNT);
    int i = blockIdx.x * blockDim.x + threadIdx.x;
    int stride = gridDim.x * blockDim.x;
    for (; i < E; i += stride) atomicAdd(&cnt[ei[E + i]], 1);
}

// ---------------- prefix sum over counts -> row_ptr ----------------------------
__global__ void prefix_kernel() {
    __shared__ int sh[1024];
    __shared__ int carry;
    const int tid = threadIdx.x;
    int* rp = (int*)(g_scratch + OFF_RP);
    const int* cnt = (const int*)(g_scratch + OFF_CNT);
    if (tid == 0) { carry = 0; rp[0] = 0; }
    __syncthreads();
    for (int base = 0; base < NN; base += 1024) {
        int i = base + tid;
        int v = (i < NN) ? cnt[i] : 0;
        sh[tid] = v;
        __syncthreads();
        for (int off = 1; off < 1024; off <<= 1) {
            int t = (tid >= off) ? sh[tid - off] : 0;
            __syncthreads();
            sh[tid] += t;
            __syncthreads();
        }
        if (i < NN) rp[i + 1] = carry + sh[tid];
        __syncthreads();
        if (tid == 0) carry += sh[1023];
        __syncthreads();
    }
}

// ---------------- fill CSR ------------------------------------------------------
__global__ void fillcsr_kernel(const int* __restrict__ ei, int E) {
    const int* rp = (const int*)(g_scratch + OFF_RP);
    int* fill = (int*)(g_scratch + OFF_FILL);
    int* csr = (int*)(g_scratch + OFF_CSR);
    int i = blockIdx.x * blockDim.x + threadIdx.x;
    int stride = gridDim.x * blockDim.x;
    for (; i < E; i += stride) {
        int s = ei[i];
        int t = ei[E + i];
        int pos = rp[t] + atomicAdd(&fill[t], 1);
        csr[pos] = s;
    }
}

// ---------------- gather-mean (warp per node) -----------------------------------
__global__ void gather_kernel(int xoff, const float* __restrict__ xext, int d) {
    const float* x = bufp(xoff, xext);
    float* agg = g_scratch + OFF_AGG;
    const int* rp = (const int*)(g_scratch + OFF_RP);
    const int* csr = (const int*)(g_scratch + OFF_CSR);
    int node = (blockIdx.x * blockDim.x + threadIdx.x) >> 5;
    int lane = threadIdx.x & 31;
    if (node >= NN) return;
    int beg = rp[node], end = rp[node + 1];
    const int nv = d >> 7;

    float4 acc[4];
#pragma unroll
    for (int v = 0; v < 4; v++) acc[v] = make_float4(0.f, 0.f, 0.f, 0.f);

    int e = beg;
    for (; e + 1 < end; e += 2) {
        const float* x0 = x + (size_t)csr[e] * d;
        const float* x1 = x + (size_t)csr[e + 1] * d;
#pragma unroll 4
        for (int v = 0; v < nv; v++) {
            float4 a = *(const float4*)(x0 + lane * 4 + v * 128);
            float4 b = *(const float4*)(x1 + lane * 4 + v * 128);
            acc[v].x += a.x + b.x; acc[v].y += a.y + b.y;
            acc[v].z += a.z + b.z; acc[v].w += a.w + b.w;
        }
    }
    if (e < end) {
        const float* x0 = x + (size_t)csr[e] * d;
#pragma unroll 4
        for (int v = 0; v < nv; v++) {
            float4 a = *(const float4*)(x0 + lane * 4 + v * 128);
            acc[v].x += a.x; acc[v].y += a.y; acc[v].z += a.z; acc[v].w += a.w;
        }
    }
    float sc = 1.0f / (float)max(end - beg, 1);
    float* out = agg + (size_t)node * d + lane * 4;
#pragma unroll 4
    for (int v = 0; v < nv; v++) {
        float4 o;
        o.x = f2tf(acc[v].x * sc); o.y = f2tf(acc[v].y * sc);
        o.z = f2tf(acc[v].z * sc); o.w = f2tf(acc[v].w * sc);
        *(float4*)(out + v * 128) = o;
    }
}

// ---------------- merged weight transpose (+tf32) -------------------------------
__global__ void transall_kernel(const float* __restrict__ W1l, const float* __restrict__ W1r,
                                const float* __restrict__ W2l, const float* __restrict__ W2r,
                                const float* __restrict__ W3l, const float* __restrict__ W3r,
                                const float* __restrict__ Wfc) {
    __shared__ float t[32][33];
    int b = blockIdx.x;
    const float* src; int dstOff, K, N, lt;
    if      (b < 128)  { src = W1l; dstOff = OFF_W1L; K = 256;  N = 512;  lt = b; }
    else if (b < 256)  { src = W1r; dstOff = OFF_W1R; K = 256;  N = 512;  lt = b - 128; }
    else if (b < 512)  { src = W2l; dstOff = OFF_W2L; K = 512;  N = 512;  lt = b - 256; }
    else if (b < 768)  { src = W2r; dstOff = OFF_W2R; K = 512;  N = 512;  lt = b - 512; }
    else if (b < 1280) { src = W3l; dstOff = OFF_W3L; K = 512;  N = 1024; lt = b - 768; }
    else if (b < 1792) { src = W3r; dstOff = OFF_W3R; K = 512;  N = 1024; lt = b - 1280; }
    else               { src = Wfc; dstOff = OFF_WFC; K = 1024; N = 512;  lt = b - 1792; }
    int ntx = N >> 5;
    int nb = (lt % ntx) * 32, kb = (lt / ntx) * 32;
    int tx = threadIdx.x, ty = threadIdx.y;
    for (int i = ty; i < 32; i += 8)
        t[i][tx] = src[(size_t)(kb + i) * N + nb + tx];
    __syncthreads();
    float* dst = g_scratch + dstOff;
    for (int i = ty; i < 32; i += 8)
        dst[(size_t)(nb + i) * K + kb + tx] = f2tf(t[tx][i]);
}

// ---------------- tf32-round copy ------------------------------------------------
__global__ void cvt_kernel(const float* __restrict__ src, int dstOff, int n4) {
    float4* dst = (float4*)(g_scratch + dstOff);
    int i = blockIdx.x * blockDim.x + threadIdx.x;
    int stride = gridDim.x * blockDim.x;
    for (; i < n4; i += stride) {
        float4 v = ((const float4*)src)[i];
        v.x = f2tf(v.x); v.y = f2tf(v.y); v.z = f2tf(v.z); v.w = f2tf(v.w);
        dst[i] = v;
    }
}

// ---------------- tf32 mma.sync GEMM, 4-stage cp.async (R10 config) ------------
// CTA tile 128x128, 256 threads = 8 warps (2 M x 4 N), warp tile 64x32, BK=16.
// __launch_bounds__(256, 2): force <=128 regs so 2 CTAs/SM are guaranteed.
#define BM 128
#define BN 128
#define BKC 16
#define PADR 20
#define NSTG 4
#define STG_F (BM * PADR)
#define SMEM_GEMM (NSTG * STG_F * 2 * 4)

__global__ __launch_bounds__(256, 2)
void gemm_mma(int a1off, const float* a1ext, int a2off, const float* a2ext, int hasA2,
              int b1off, int b2off, const float* __restrict__ bias,
              int coff, float* cext, int M, int N, int K, int doRelu, int doRound) {
    extern __shared__ float sm[];
    float* sA = sm;
    float* sB = sm + NSTG * STG_F;

    const float* A1 = bufp(a1off, a1ext);
    const float* A2 = bufp(a2off, a2ext);
    const float* B1 = g_scratch + b1off;
    const float* B2 = g_scratch + b2off;
    float* C = bufp(coff, cext);

    const int tid = threadIdx.x, wid = tid >> 5, lane = tid & 31;
    const int rowBase = blockIdx.y * BM;
    const int colBase = blockIdx.x * BN;
    const int wm = (wid >> 2) * 64;
    const int wn = (wid & 3) * 32;
    const int lr = tid >> 2;
    const int lc4 = (tid & 3) * 4;
    const int qrow = lane >> 2;
    const int qcol = lane & 3;

    const uint32_t sAu = smem_u32(sA);
    const uint32_t sBu = smem_u32(sB);

    float acc[4][4][4];
#pragma unroll
    for (int mi = 0; mi < 4; mi++)
#pragma unroll
        for (int ni = 0; ni < 4; ni++)
#pragma unroll
            for (int r = 0; r < 4; r++) acc[mi][ni][r] = 0.f;

    const int Ktot = hasA2 ? 2 * K : K;
    const int nch = Ktot / BKC;

    auto load_stage = [&](int c) {
        int stg = c & (NSTG - 1);
        int k0 = c * BKC;
        const float* A; const float* B; int kk;
        if (k0 < K) { A = A1; B = B1; kk = k0; }
        else        { A = A2; B = B2; kk = k0 - K; }
#pragma unroll
        for (int p = 0; p < 2; p++) {
            int row = lr + p * 64;
            int gm = rowBase + row;
            const float* src = A + (size_t)gm * K + kk + lc4;
            uint32_t dst = sAu + (uint32_t)(stg * STG_F + row * PADR + lc4) * 4u;
            uint32_t sz = (gm < M) ? 16u : 0u;
            asm volatile("cp.async.cg.shared.global [%0], [%1], 16, %2;"
                         :: "r"(dst), "l"(src), "r"(sz));
        }
#pragma unroll
        for (int p = 0; p < 2; p++) {
            int row = lr + p * 64;
            const float* src = B + (size_t)(colBase + row) * K + kk + lc4;
            uint32_t dst = sBu + (uint32_t)(stg * STG_F + row * PADR + lc4) * 4u;
            asm volatile("cp.async.cg.shared.global [%0], [%1], 16, %2;"
                         :: "r"(dst), "l"(src), "r"(16u));
        }
    };

#pragma unroll
    for (int i = 0; i < NSTG - 1; i++) {
        if (i < nch) load_stage(i);
        asm volatile("cp.async.commit_group;" ::: "memory");
    }

    for (int ch = 0; ch < nch; ch++) {
        asm volatile("cp.async.wait_group 2;" ::: "memory");
        __syncthreads();

        int pre = ch + NSTG - 1;
        if (pre < nch) load_stage(pre);
        asm volatile("cp.async.commit_group;" ::: "memory");

        const float* As = sA + (ch & (NSTG - 1)) * STG_F;
        const float* Bs = sB + (ch & (NSTG - 1)) * STG_F;
#pragma unroll
        for (int ks = 0; ks < 2; ks++) {
            const int kof = ks * 8;
            uint32_t af[4][4], bf[4][2];
#pragma unroll
            for (int mi = 0; mi < 4; mi++) {
                int r0 = wm + mi * 16 + qrow;
                int c0 = kof + qcol;
                af[mi][0] = __float_as_uint(As[r0 * PADR + c0]);
                af[mi][1] = __float_as_uint(As[(r0 + 8) * PADR + c0]);
                af[mi][2] = __float_as_uint(As[r0 * PADR + c0 + 4]);
                af[mi][3] = __float_as_uint(As[(r0 + 8) * PADR + c0 + 4]);
            }
#pragma unroll
            for (int ni = 0; ni < 4; ni++) {
                int cn = wn + ni * 8 + qrow;
                int rk = kof + qcol;
                bf[ni][0] = __float_as_uint(Bs[cn * PADR + rk]);
                bf[ni][1] = __float_as_uint(Bs[cn * PADR + rk + 4]);
            }
#pragma unroll
            for (int mi = 0; mi < 4; mi++)
#pragma unroll
                for (int ni = 0; ni < 4; ni++) {
                    asm volatile(
                        "mma.sync.aligned.m16n8k8.row.col.f32.tf32.tf32.f32 "
                        "{%0,%1,%2,%3}, {%4,%5,%6,%7}, {%8,%9}, {%0,%1,%2,%3};"
                        : "+f"(acc[mi][ni][0]), "+f"(acc[mi][ni][1]),
                          "+f"(acc[mi][ni][2]), "+f"(acc[mi][ni][3])
                        : "r"(af[mi][0]), "r"(af[mi][1]), "r"(af[mi][2]), "r"(af[mi][3]),
                          "r"(bf[ni][0]), "r"(bf[ni][1]));
                }
        }
    }

#pragma unroll
    for (int mi = 0; mi < 4; mi++) {
        int gm0 = rowBase + wm + mi * 16 + qrow;
        int gm1 = gm0 + 8;
#pragma unroll
        for (int ni = 0; ni < 4; ni++) {
            int col = colBase + wn + ni * 8 + 2 * qcol;
            float2 bv = *(const float2*)(bias + col);
            float r0 = acc[mi][ni][0] + bv.x;
            float r1 = acc[mi][ni][1] + bv.y;
            float r2 = acc[mi][ni][2] + bv.x;
            float r3 = acc[mi][ni][3] + bv.y;
            if (doRelu) {
                r0 = fmaxf(r0, 0.f); r1 = fmaxf(r1, 0.f);
                r2 = fmaxf(r2, 0.f); r3 = fmaxf(r3, 0.f);
            }
            if (doRound) {
                r0 = f2tf(r0); r1 = f2tf(r1); r2 = f2tf(r2); r3 = f2tf(r3);
            }
            if (gm0 < M) *(float2*)(C + (size_t)gm0 * N + col) = make_float2(r0, r1);
            if (gm1 < M) *(float2*)(C + (size_t)gm1 * N + col) = make_float2(r2, r3);
        }
    }
}

// ---------------- launch --------------------------------------------------------
extern "C" void kernel_launch(void* const* d_in, const int* in_sizes, int n_in,
                              void* d_out, int out_size) {
    const float* x   = (const float*)d_in[0];
    const int*   ei  = (const int*)d_in[1];
    const float* Wl1 = (const float*)d_in[2];
    const float* bl1 = (const float*)d_in[3];
    const float* Wr1 = (const float*)d_in[4];
    const float* Wl2 = (const float*)d_in[5];
    const float* bl2 = (const float*)d_in[6];
    const float* Wr2 = (const float*)d_in[7];
    const float* Wl3 = (const float*)d_in[8];
    const float* bl3 = (const float*)d_in[9];
    const float* Wr3 = (const float*)d_in[10];
    const float* Wfc = (const float*)d_in[11];
    const float* bfc = (const float*)d_in[12];
    float* out = (float*)d_out;

    cudaFuncSetAttribute(gemm_mma, cudaFuncAttributeMaxDynamicSharedMemorySize, SMEM_GEMM);

    const int M = NN, E = NE;
    dim3 tb(32, 8);

    transall_kernel<<<2304, tb>>>(Wl1, Wr1, Wl2, Wr2, Wl3, Wr3, Wfc);
    cvt_kernel<<<1250, 256>>>(x, OFF_XC, NN * 256 / 4);

    zero2_kernel<<<40, 256>>>(OFF_CNT, SZ_CNT / 4, OFF_FILL, 20480 / 4);
    count_kernel<<<1250, 256>>>(ei, E);
    prefix_kernel<<<1, 1024>>>();
    fillcsr_kernel<<<1250, 256>>>(ei, E);

    const int gatherBlocks = (NN * 32 + 255) / 256;
    const int gy = (M + BM - 1) / BM;   // 157

    // ---- layer 1: 256 -> 512
    gather_kernel<<<gatherBlocks, 256>>>(-1, x, 256);
    gemm_mma<<<dim3(512 / BN, gy), 256, SMEM_GEMM>>>(
        OFF_AGG, nullptr, OFF_XC, nullptr, 1, OFF_W1L, OFF_W1R, bl1,
        OFF_H1, nullptr, M, 512, 256, 1, 1);

    // ---- layer 2: 512 -> 512
    gather_kernel<<<gatherBlocks, 256>>>(OFF_H1, nullptr, 512);
    gemm_mma<<<dim3(512 / BN, gy), 256, SMEM_GEMM>>>(
        OFF_AGG, nullptr, OFF_H1, nullptr, 1, OFF_W2L, OFF_W2R, bl2,
        OFF_H2, nullptr, M, 512, 512, 1, 1);

    // ---- layer 3: 512 -> 1024
    gather_kernel<<<gatherBlocks, 256>>>(OFF_H2, nullptr, 512);
    gemm_mma<<<dim3(1024 / BN, gy), 256, SMEM_GEMM>>>(
        OFF_AGG, nullptr, OFF_H2, nullptr, 1, OFF_W3L, OFF_W3R, bl3,
        OFF_H3, nullptr, M, 1024, 512, 1, 1);

    // ---- final FC: 1024 -> 512
    gemm_mma<<<dim3(512 / BN, gy), 256, SMEM_GEMM>>>(
        OFF_H3, nullptr, -1, nullptr, 0, OFF_WFC, OFF_WFC, bfc,
        -1, out, M, 512, 1024, 0, 0);
}

// round 13
// speedup vs baseline: 1.5493x; 1.5178x over previous
#include <cuda_runtime.h>
#include <cuda_fp16.h>
#include <cstdint>

#define NN 20000
#define NE 320000

// ---------------- single aligned device scratch (float-unit offsets) ----------
// Buffers now hold __half; float-sized regions are >= needed (2x slack).
#define OFF_CNT 0
#define SZ_CNT  20480
#define OFF_AGG (OFF_CNT + SZ_CNT)
#define SZ_AGG  (NN * 512)
#define OFF_H1  (OFF_AGG + SZ_AGG)
#define SZ_H1   (NN * 512)
#define OFF_H2  (OFF_H1 + SZ_H1)
#define SZ_H2   (NN * 512)
#define OFF_H3  (OFF_H2 + SZ_H2)
#define SZ_H3   (NN * 1024)
#define OFF_W1L (OFF_H3 + SZ_H3)
#define OFF_W1R (OFF_W1L + 512*256)
#define OFF_W2L (OFF_W1R + 512*256)
#define OFF_W2R (OFF_W2L + 512*512)
#define OFF_W3L (OFF_W2R + 512*512)
#define OFF_W3R (OFF_W3L + 1024*512)
#define OFF_WFC (OFF_W3R + 1024*512)
#define OFF_XC  (OFF_WFC + 512*1024)
#define OFF_RP   (OFF_XC + NN*256)
#define OFF_FILL (OFF_RP + 20512)
#define OFF_CSR  (OFF_FILL + 20480)
#define SZ_TOTAL (OFF_CSR + NE)

__device__ __align__(128) float g_scratch[SZ_TOTAL];

__device__ __forceinline__ uint32_t smem_u32(const void* p) {
    uint32_t a;
    asm("{ .reg .u64 t; cvta.to.shared.u64 t, %1; cvt.u32.u64 %0, t; }" : "=r"(a) : "l"(p));
    return a;
}

// ---------------- dual-region zero ---------------------------------------------
__global__ void zero2_kernel(int offA, int n4A, int offB, int n4B) {
    int i = blockIdx.x * blockDim.x + threadIdx.x;
    int stride = gridDim.x * blockDim.x;
    float4 z = make_float4(0.f, 0.f, 0.f, 0.f);
    float4* pa = (float4*)(g_scratch + offA);
    float4* pb = (float4*)(g_scratch + offB);
    for (int j = i; j < n4A; j += stride) pa[j] = z;
    for (int j = i; j < n4B; j += stride) pb[j] = z;
}

// ---------------- degree count (int) -------------------------------------------
__global__ void count_kernel(const int* __restrict__ ei, int E) {
    int* cnt = (int*)(g_scratch + OFF_CNT);
    int i = blockIdx.x * blockDim.x + threadIdx.x;
    int stride = gridDim.x * blockDim.x;
    for (; i < E; i += stride) atomicAdd(&cnt[ei[E + i]], 1);
}

// ---------------- prefix sum over counts -> row_ptr ----------------------------
__global__ void prefix_kernel() {
    __shared__ int sh[1024];
    __shared__ int carry;
    const int tid = threadIdx.x;
    int* rp = (int*)(g_scratch + OFF_RP);
    const int* cnt = (const int*)(g_scratch + OFF_CNT);
    if (tid == 0) { carry = 0; rp[0] = 0; }
    __syncthreads();
    for (int base = 0; base < NN; base += 1024) {
        int i = base + tid;
        int v = (i < NN) ? cnt[i] : 0;
        sh[tid] = v;
        __syncthreads();
        for (int off = 1; off < 1024; off <<= 1) {
            int t = (tid >= off) ? sh[tid - off] : 0;
            __syncthreads();
            sh[tid] += t;
            __syncthreads();
        }
        if (i < NN) rp[i + 1] = carry + sh[tid];
        __syncthreads();
        if (tid == 0) carry += sh[1023];
        __syncthreads();
    }
}

// ---------------- fill CSR ------------------------------------------------------
__global__ void fillcsr_kernel(const int* __restrict__ ei, int E) {
    const int* rp = (const int*)(g_scratch + OFF_RP);
    int* fill = (int*)(g_scratch + OFF_FILL);
    int* csr = (int*)(g_scratch + OFF_CSR);
    int i = blockIdx.x * blockDim.x + threadIdx.x;
    int stride = gridDim.x * blockDim.x;
    for (; i < E; i += stride) {
        int s = ei[i];
        int t = ei[E + i];
        int pos = rp[t] + atomicAdd(&fill[t], 1);
        csr[pos] = s;
    }
}

// ---------------- gather-mean layer1: fp32 x in, fp16 agg out -------------------
__global__ void gather_f32(const float* __restrict__ x, int d) {
    __half* agg = (__half*)(g_scratch + OFF_AGG);
    const int* rp = (const int*)(g_scratch + OFF_RP);
    const int* csr = (const int*)(g_scratch + OFF_CSR);
    int node = (blockIdx.x * blockDim.x + threadIdx.x) >> 5;
    int lane = threadIdx.x & 31;
    if (node >= NN) return;
    int beg = rp[node], end = rp[node + 1];
    const int nv = d >> 7;   // float4 per lane per pass (d=256 -> 2)

    float4 acc[2];
#pragma unroll
    for (int v = 0; v < 2; v++) acc[v] = make_float4(0.f, 0.f, 0.f, 0.f);

    int e = beg;
    for (; e + 1 < end; e += 2) {
        const float* x0 = x + (size_t)csr[e] * d;
        const float* x1 = x + (size_t)csr[e + 1] * d;
#pragma unroll 2
        for (int v = 0; v < nv; v++) {
            float4 a = *(const float4*)(x0 + lane * 4 + v * 128);
            float4 b = *(const float4*)(x1 + lane * 4 + v * 128);
            acc[v].x += a.x + b.x; acc[v].y += a.y + b.y;
            acc[v].z += a.z + b.z; acc[v].w += a.w + b.w;
        }
    }
    if (e < end) {
        const float* x0 = x + (size_t)csr[e] * d;
#pragma unroll 2
        for (int v = 0; v < nv; v++) {
            float4 a = *(const float4*)(x0 + lane * 4 + v * 128);
            acc[v].x += a.x; acc[v].y += a.y; acc[v].z += a.z; acc[v].w += a.w;
        }
    }
    float sc = 1.0f / (float)max(end - beg, 1);
    __half* out = agg + (size_t)node * d + lane * 4;
#pragma unroll 2
    for (int v = 0; v < nv; v++) {
        half2 h0 = __floats2half2_rn(acc[v].x * sc, acc[v].y * sc);
        half2 h1 = __floats2half2_rn(acc[v].z * sc, acc[v].w * sc);
        *(half2*)(out + v * 128) = h0;
        *(half2*)(out + v * 128 + 2) = h1;
    }
}

// ---------------- gather-mean layers 2/3: fp16 h in, fp16 agg out ---------------
__global__ void gather_f16(int xoff, int d) {   // d halves (512)
    const __half* x = (const __half*)(g_scratch + xoff);
    __half* agg = (__half*)(g_scratch + OFF_AGG);
    const int* rp = (const int*)(g_scratch + OFF_RP);
    const int* csr = (const int*)(g_scratch + OFF_CSR);
    int node = (blockIdx.x * blockDim.x + threadIdx.x) >> 5;
    int lane = threadIdx.x & 31;
    if (node >= NN) return;
    int beg = rp[node], end = rp[node + 1];
    const int nv = d >> 8;   // uint4 (8 halves) per lane per pass: d=512 -> 2

    float2 acc[8];           // 16 floats
#pragma unroll
    for (int v = 0; v < 8; v++) acc[v] = make_float2(0.f, 0.f);

    for (int e = beg; e < end; e++) {
        const __half* x0 = x + (size_t)csr[e] * d;
#pragma unroll 2
        for (int v = 0; v < nv; v++) {
            uint4 raw = *(const uint4*)(x0 + lane * 8 + v * 256);
            half2 p0 = *(half2*)&raw.x, p1 = *(half2*)&raw.y;
            half2 p2 = *(half2*)&raw.z, p3 = *(half2*)&raw.w;
            float2 f0 = __half22float2(p0), f1 = __half22float2(p1);
            float2 f2 = __half22float2(p2), f3 = __half22float2(p3);
            acc[v*4+0].x += f0.x; acc[v*4+0].y += f0.y;
            acc[v*4+1].x += f1.x; acc[v*4+1].y += f1.y;
            acc[v*4+2].x += f2.x; acc[v*4+2].y += f2.y;
            acc[v*4+3].x += f3.x; acc[v*4+3].y += f3.y;
        }
    }
    float sc = 1.0f / (float)max(end - beg, 1);
    __half* out = agg + (size_t)node * d + lane * 8;
#pragma unroll 2
    for (int v = 0; v < nv; v++) {
        uint4 w;
        half2 h0 = __floats2half2_rn(acc[v*4+0].x * sc, acc[v*4+0].y * sc);
        half2 h1 = __floats2half2_rn(acc[v*4+1].x * sc, acc[v*4+1].y * sc);
        half2 h2 = __floats2half2_rn(acc[v*4+2].x * sc, acc[v*4+2].y * sc);
        half2 h3 = __floats2half2_rn(acc[v*4+3].x * sc, acc[v*4+3].y * sc);
        w.x = *(uint32_t*)&h0; w.y = *(uint32_t*)&h1;
        w.z = *(uint32_t*)&h2; w.w = *(uint32_t*)&h3;
        *(uint4*)(out + v * 256) = w;
    }
}

// ---------------- merged weight transpose -> fp16 -------------------------------
__global__ void transall_kernel(const float* __restrict__ W1l, const float* __restrict__ W1r,
                                const float* __restrict__ W2l, const float* __restrict__ W2r,
                                const float* __restrict__ W3l, const float* __restrict__ W3r,
                                const float* __restrict__ Wfc) {
    __shared__ float t[32][33];
    int b = blockIdx.x;
    const float* src; int dstOff, K, N, lt;
    if      (b < 128)  { src = W1l; dstOff = OFF_W1L; K = 256;  N = 512;  lt = b; }
    else if (b < 256)  { src = W1r; dstOff = OFF_W1R; K = 256;  N = 512;  lt = b - 128; }
    else if (b < 512)  { src = W2l; dstOff = OFF_W2L; K = 512;  N = 512;  lt = b - 256; }
    else if (b < 768)  { src = W2r; dstOff = OFF_W2R; K = 512;  N = 512;  lt = b - 512; }
    else if (b < 1280) { src = W3l; dstOff = OFF_W3L; K = 512;  N = 1024; lt = b - 768; }
    else if (b < 1792) { src = W3r; dstOff = OFF_W3R; K = 512;  N = 1024; lt = b - 1280; }
    else               { src = Wfc; dstOff = OFF_WFC; K = 1024; N = 512;  lt = b - 1792; }
    int ntx = N >> 5;
    int nb = (lt % ntx) * 32, kb = (lt / ntx) * 32;
    int tx = threadIdx.x, ty = threadIdx.y;
    for (int i = ty; i < 32; i += 8)
        t[i][tx] = src[(size_t)(kb + i) * N + nb + tx];
    __syncthreads();
    __half* dst = (__half*)(g_scratch + dstOff);
    for (int i = ty; i < 32; i += 8)
        dst[(size_t)(nb + i) * K + kb + tx] = __float2half_rn(t[tx][i]);
}

// ---------------- fp16 copy of x -------------------------------------------------
__global__ void cvt_kernel(const float* __restrict__ src, int n4) {
    __half* dst = (__half*)(g_scratch + OFF_XC);
    int i = blockIdx.x * blockDim.x + threadIdx.x;
    int stride = gridDim.x * blockDim.x;
    for (; i < n4; i += stride) {
        float4 v = ((const float4*)src)[i];
        half2 h0 = __floats2half2_rn(v.x, v.y);
        half2 h1 = __floats2half2_rn(v.z, v.w);
        uint32_t w0 = *(uint32_t*)&h0, w1 = *(uint32_t*)&h1;
        uint2 w; w.x = w0; w.y = w1;
        *(uint2*)(dst + i * 4) = w;
    }
}

// ---------------- fp16 mma.sync GEMM, 4-stage cp.async ---------------------------
// CTA tile 128x128, 256 threads = 8 warps (2M x 4N), warp tile 64x32.
// BKC=32 halves/chunk (2 ksteps of m16n8k16). smem rows padded to 40 halves
// (word-stride 20: banks 20r+c all distinct for r<8,c<4 -> conflict-free).
#define BM 128
#define BN 128
#define BKC 32
#define PADH 40
#define NSTG 4
#define STG_H (BM * PADH)                 /* halves per stage per matrix */
#define SMEM_GEMM (NSTG * STG_H * 2 * 2)  /* bytes = 81920 */

__global__ __launch_bounds__(256, 2)
void gemm_mma(int a1off, int a2off, int hasA2,
              int b1off, int b2off, const float* __restrict__ bias,
              int coff, float* cext, int M, int N, int K, int doRelu, int outHalf) {
    extern __shared__ __half smh[];
    __half* sA = smh;
    __half* sB = smh + NSTG * STG_H;

    const __half* A1 = (const __half*)(g_scratch + a1off);
    const __half* A2 = (const __half*)(g_scratch + a2off);
    const __half* B1 = (const __half*)(g_scratch + b1off);
    const __half* B2 = (const __half*)(g_scratch + b2off);
    float* Cf = (coff >= 0) ? (g_scratch + coff) : cext;
    __half* Ch = (__half*)Cf;

    const int tid = threadIdx.x, wid = tid >> 5, lane = tid & 31;
    const int rowBase = blockIdx.y * BM;
    const int colBase = blockIdx.x * BN;
    const int wm = (wid >> 2) * 64;
    const int wn = (wid & 3) * 32;
    const int lr = tid >> 2;            // 0..63
    const int lc8 = (tid & 3) * 8;      // halves: 0,8,16,24 (16B)
    const int qrow = lane >> 2;
    const int qcol = lane & 3;

    const uint32_t sAu = smem_u32(sA);
    const uint32_t sBu = smem_u32(sB);

    float acc[4][4][4];
#pragma unroll
    for (int mi = 0; mi < 4; mi++)
#pragma unroll
        for (int ni = 0; ni < 4; ni++)
#pragma unroll
            for (int r = 0; r < 4; r++) acc[mi][ni][r] = 0.f;

    const int Ktot = hasA2 ? 2 * K : K;
    const int nch = Ktot / BKC;

    auto load_stage = [&](int c) {
        int stg = c & (NSTG - 1);
        int k0 = c * BKC;
        const __half* A; const __half* B; int kk;
        if (k0 < K) { A = A1; B = B1; kk = k0; }
        else        { A = A2; B = B2; kk = k0 - K; }
#pragma unroll
        for (int p = 0; p < 2; p++) {
            int row = lr + p * 64;
            int gm = rowBase + row;
            const __half* src = A + (size_t)gm * K + kk + lc8;
            uint32_t dst = sAu + (uint32_t)(stg * STG_H + row * PADH + lc8) * 2u;
            uint32_t sz = (gm < M) ? 16u : 0u;
            asm volatile("cp.async.cg.shared.global [%0], [%1], 16, %2;"
                         :: "r"(dst), "l"(src), "r"(sz));
        }
#pragma unroll
        for (int p = 0; p < 2; p++) {
            int row = lr + p * 64;
            const __half* src = B + (size_t)(colBase + row) * K + kk + lc8;
            uint32_t dst = sBu + (uint32_t)(stg * STG_H + row * PADH + lc8) * 2u;
            asm volatile("cp.async.cg.shared.global [%0], [%1], 16, %2;"
                         :: "r"(dst), "l"(src), "r"(16u));
        }
    };

#pragma unroll
    for (int i = 0; i < NSTG - 1; i++) {
        if (i < nch) load_stage(i);
        asm volatile("cp.async.commit_group;" ::: "memory");
    }

    for (int ch = 0; ch < nch; ch++) {
        asm volatile("cp.async.wait_group 2;" ::: "memory");
        __syncthreads();

        int pre = ch + NSTG - 1;
        if (pre < nch) load_stage(pre);
        asm volatile("cp.async.commit_group;" ::: "memory");

        const __half* As = sA + (ch & (NSTG - 1)) * STG_H;
        const __half* Bs = sB + (ch & (NSTG - 1)) * STG_H;
#pragma unroll
        for (int ks = 0; ks < 2; ks++) {
            const int kof = ks * 16;
            uint32_t af[4][4], bf[4][2];
#pragma unroll
            for (int mi = 0; mi < 4; mi++) {
                int r0 = wm + mi * 16 + qrow;
                int c0 = kof + 2 * qcol;
                af[mi][0] = *(const uint32_t*)&As[r0 * PADH + c0];
                af[mi][1] = *(const uint32_t*)&As[(r0 + 8) * PADH + c0];
                af[mi][2] = *(const uint32_t*)&As[r0 * PADH + c0 + 8];
                af[mi][3] = *(const uint32_t*)&As[(r0 + 8) * PADH + c0 + 8];
            }
#pragma unroll
            for (int ni = 0; ni < 4; ni++) {
                int cn = wn + ni * 8 + qrow;
                int rk = kof + 2 * qcol;
                bf[ni][0] = *(const uint32_t*)&Bs[cn * PADH + rk];
                bf[ni][1] = *(const uint32_t*)&Bs[cn * PADH + rk + 8];
            }
#pragma unroll
            for (int mi = 0; mi < 4; mi++)
#pragma unroll
                for (int ni = 0; ni < 4; ni++) {
                    asm volatile(
                        "mma.sync.aligned.m16n8k16.row.col.f32.f16.f16.f32 "
                        "{%0,%1,%2,%3}, {%4,%5,%6,%7}, {%8,%9}, {%0,%1,%2,%3};"
                        : "+f"(acc[mi][ni][0]), "+f"(acc[mi][ni][1]),
                          "+f"(acc[mi][ni][2]), "+f"(acc[mi][ni][3])
                        : "r"(af[mi][0]), "r"(af[mi][1]), "r"(af[mi][2]), "r"(af[mi][3]),
                          "r"(bf[ni][0]), "r"(bf[ni][1]));
                }
        }
    }

#pragma unroll
    for (int mi = 0; mi < 4; mi++) {
        int gm0 = rowBase + wm + mi * 16 + qrow;
        int gm1 = gm0 + 8;
#pragma unroll
        for (int ni = 0; ni < 4; ni++) {
            int col = colBase + wn + ni * 8 + 2 * qcol;
            float2 bv = *(const float2*)(bias + col);
            float r0 = acc[mi][ni][0] + bv.x;
            float r1 = acc[mi][ni][1] + bv.y;
            float r2 = acc[mi][ni][2] + bv.x;
            float r3 = acc[mi][ni][3] + bv.y;
            if (doRelu) {
                r0 = fmaxf(r0, 0.f); r1 = fmaxf(r1, 0.f);
                r2 = fmaxf(r2, 0.f); r3 = fmaxf(r3, 0.f);
            }
            if (outHalf) {
                half2 h0 = __floats2half2_rn(r0, r1);
                half2 h1 = __floats2half2_rn(r2, r3);
                if (gm0 < M) *(half2*)(Ch + (size_t)gm0 * N + col) = h0;
                if (gm1 < M) *(half2*)(Ch + (size_t)gm1 * N + col) = h1;
            } else {
                if (gm0 < M) *(float2*)(Cf + (size_t)gm0 * N + col) = make_float2(r0, r1);
                if (gm1 < M) *(float2*)(Cf + (size_t)gm1 * N + col) = make_float2(r2, r3);
            }
        }
    }
}

// ---------------- launch --------------------------------------------------------
extern "C" void kernel_launch(void* const* d_in, const int* in_sizes, int n_in,
                              void* d_out, int out_size) {
    const float* x   = (const float*)d_in[0];
    const int*   ei  = (const int*)d_in[1];
    const float* Wl1 = (const float*)d_in[2];
    const float* bl1 = (const float*)d_in[3];
    const float* Wr1 = (const float*)d_in[4];
    const float* Wl2 = (const float*)d_in[5];
    const float* bl2 = (const float*)d_in[6];
    const float* Wr2 = (const float*)d_in[7];
    const float* Wl3 = (const float*)d_in[8];
    const float* bl3 = (const float*)d_in[9];
    const float* Wr3 = (const float*)d_in[10];
    const float* Wfc = (const float*)d_in[11];
    const float* bfc = (const float*)d_in[12];
    float* out = (float*)d_out;

    cudaFuncSetAttribute(gemm_mma, cudaFuncAttributeMaxDynamicSharedMemorySize, SMEM_GEMM);

    const int M = NN, E = NE;
    dim3 tb(32, 8);

    transall_kernel<<<2304, tb>>>(Wl1, Wr1, Wl2, Wr2, Wl3, Wr3, Wfc);
    cvt_kernel<<<1250, 256>>>(x, NN * 256 / 4);

    zero2_kernel<<<40, 256>>>(OFF_CNT, SZ_CNT / 4, OFF_FILL, 20480 / 4);
    count_kernel<<<1250, 256>>>(ei, E);
    prefix_kernel<<<1, 1024>>>();
    fillcsr_kernel<<<1250, 256>>>(ei, E);

    const int gatherBlocks = (NN * 32 + 255) / 256;
    const int gy = (M + BM - 1) / BM;   // 157

    // ---- layer 1: 256 -> 512
    gather_f32<<<gatherBlocks, 256>>>(x, 256);
    gemm_mma<<<dim3(512 / BN, gy), 256, SMEM_GEMM>>>(
        OFF_AGG, OFF_XC, 1, OFF_W1L, OFF_W1R, bl1,
        OFF_H1, nullptr, M, 512, 256, 1, 1);

    // ---- layer 2: 512 -> 512
    gather_f16<<<gatherBlocks, 256>>>(OFF_H1, 512);
    gemm_mma<<<dim3(512 / BN, gy), 256, SMEM_GEMM>>>(
        OFF_AGG, OFF_H1, 1, OFF_W2L, OFF_W2R, bl2,
        OFF_H2, nullptr, M, 512, 512, 1, 1);

    // ---- layer 3: 512 -> 1024
    gather_f16<<<gatherBlocks, 256>>>(OFF_H2, 512);
    gemm_mma<<<dim3(1024 / BN, gy), 256, SMEM_GEMM>>>(
        OFF_AGG, OFF_H2, 1, OFF_W3L, OFF_W3R, bl3,
        OFF_H3, nullptr, M, 1024, 512, 1, 1);

    // ---- final FC: 1024 -> 512 (fp32 out)
    gemm_mma<<<dim3(512 / BN, gy), 256, SMEM_GEMM>>>(
        OFF_H3, OFF_H3, 0, OFF_WFC, OFF_WFC, bfc,
        -1, out, M, 512, 1024, 0, 0);
}

// round 14
// speedup vs baseline: 1.8497x; 1.1939x over previous
#include <cuda_runtime.h>
#include <cuda_fp16.h>
#include <cstdint>

#define NN 20000
#define NE 320000

// ---------------- single aligned device scratch (float-unit offsets) ----------
#define OFF_CNT 0
#define SZ_CNT  20480
#define OFF_AGG (OFF_CNT + SZ_CNT)
#define SZ_AGG  (NN * 512)
#define OFF_H1  (OFF_AGG + SZ_AGG)
#define SZ_H1   (NN * 512)
#define OFF_H2  (OFF_H1 + SZ_H1)
#define SZ_H2   (NN * 512)
#define OFF_H3  (OFF_H2 + SZ_H2)
#define SZ_H3   (NN * 1024)
#define OFF_W1L (OFF_H3 + SZ_H3)
#define OFF_W1R (OFF_W1L + 512*256)
#define OFF_W2L (OFF_W1R + 512*256)
#define OFF_W2R (OFF_W2L + 512*512)
#define OFF_W3L (OFF_W2R + 512*512)
#define OFF_W3R (OFF_W3L + 1024*512)
#define OFF_WFC (OFF_W3R + 1024*512)
#define OFF_XC  (OFF_WFC + 512*1024)
#define OFF_RP   (OFF_XC + NN*256)
#define OFF_FILL (OFF_RP + 20512)
#define OFF_CSR  (OFF_FILL + 20480)
#define SZ_TOTAL (OFF_CSR + NE)

__device__ __align__(128) float g_scratch[SZ_TOTAL];

__device__ __forceinline__ uint32_t smem_u32(const void* p) {
    uint32_t a;
    asm("{ .reg .u64 t; cvta.to.shared.u64 t, %1; cvt.u32.u64 %0, t; }" : "=r"(a) : "l"(p));
    return a;
}

// ---------------- dual-region zero ---------------------------------------------
__global__ void zero2_kernel(int offA, int n4A, int offB, int n4B) {
    int i = blockIdx.x * blockDim.x + threadIdx.x;
    int stride = gridDim.x * blockDim.x;
    float4 z = make_float4(0.f, 0.f, 0.f, 0.f);
    float4* pa = (float4*)(g_scratch + offA);
    float4* pb = (float4*)(g_scratch + offB);
    for (int j = i; j < n4A; j += stride) pa[j] = z;
    for (int j = i; j < n4B; j += stride) pb[j] = z;
}

// ---------------- degree count (int) -------------------------------------------
__global__ void count_kernel(const int* __restrict__ ei, int E) {
    int* cnt = (int*)(g_scratch + OFF_CNT);
    int i = blockIdx.x * blockDim.x + threadIdx.x;
    int stride = gridDim.x * blockDim.x;
    for (; i < E; i += stride) atomicAdd(&cnt[ei[E + i]], 1);
}

// ---------------- prefix sum (chunked, warp-shfl block scan) --------------------
#define PCH 20
__global__ void prefix_kernel() {
    const int tid = threadIdx.x;
    int* rp = (int*)(g_scratch + OFF_RP);
    const int* cnt = (const int*)(g_scratch + OFF_CNT);
    int beg = tid * PCH;
    int local[PCH];
    int s = 0;
#pragma unroll
    for (int j = 0; j < PCH; j++) {
        int i = beg + j;
        int v = (i < NN) ? cnt[i] : 0;
        local[j] = v; s += v;
    }
    int lane = tid & 31, wid = tid >> 5;
    int sc = s;
#pragma unroll
    for (int o = 1; o < 32; o <<= 1) {
        int t = __shfl_up_sync(~0u, sc, o);
        if (lane >= o) sc += t;
    }
    __shared__ int wsum[32];
    if (lane == 31) wsum[wid] = sc;
    __syncthreads();
    if (wid == 0) {
        int w = wsum[lane];
#pragma unroll
        for (int o = 1; o < 32; o <<= 1) {
            int t = __shfl_up_sync(~0u, w, o);
            if (lane >= o) w += t;
        }
        wsum[lane] = w;
    }
    __syncthreads();
    int run = sc - s + ((wid > 0) ? wsum[wid - 1] : 0);
    if (tid == 0) rp[0] = 0;
#pragma unroll
    for (int j = 0; j < PCH; j++) {
        int i = beg + j;
        if (i < NN) { run += local[j]; rp[i + 1] = run; }
    }
}

// ---------------- fill CSR ------------------------------------------------------
__global__ void fillcsr_kernel(const int* __restrict__ ei, int E) {
    const int* rp = (const int*)(g_scratch + OFF_RP);
    int* fill = (int*)(g_scratch + OFF_FILL);
    int* csr = (int*)(g_scratch + OFF_CSR);
    int i = blockIdx.x * blockDim.x + threadIdx.x;
    int stride = gridDim.x * blockDim.x;
    for (; i < E; i += stride) {
        int s = ei[i];
        int t = ei[E + i];
        int pos = rp[t] + atomicAdd(&fill[t], 1);
        csr[pos] = s;
    }
}

// ---------------- gather-mean layer1: fp32 x in, fp16 agg out -------------------
__global__ void gather_f32(const float* __restrict__ x, int d) {
    __half* agg = (__half*)(g_scratch + OFF_AGG);
    const int* rp = (const int*)(g_scratch + OFF_RP);
    const int* csr = (const int*)(g_scratch + OFF_CSR);
    int node = (blockIdx.x * blockDim.x + threadIdx.x) >> 5;
    int lane = threadIdx.x & 31;
    if (node >= NN) return;
    int beg = rp[node], end = rp[node + 1];
    const int nv = d >> 7;

    float4 acc[2];
#pragma unroll
    for (int v = 0; v < 2; v++) acc[v] = make_float4(0.f, 0.f, 0.f, 0.f);

    int e = beg;
    for (; e + 1 < end; e += 2) {
        const float* x0 = x + (size_t)csr[e] * d;
        const float* x1 = x + (size_t)csr[e + 1] * d;
#pragma unroll 2
        for (int v = 0; v < nv; v++) {
            float4 a = *(const float4*)(x0 + lane * 4 + v * 128);
            float4 b = *(const float4*)(x1 + lane * 4 + v * 128);
            acc[v].x += a.x + b.x; acc[v].y += a.y + b.y;
            acc[v].z += a.z + b.z; acc[v].w += a.w + b.w;
        }
    }
    if (e < end) {
        const float* x0 = x + (size_t)csr[e] * d;
#pragma unroll 2
        for (int v = 0; v < nv; v++) {
            float4 a = *(const float4*)(x0 + lane * 4 + v * 128);
            acc[v].x += a.x; acc[v].y += a.y; acc[v].z += a.z; acc[v].w += a.w;
        }
    }
    float sc = 1.0f / (float)max(end - beg, 1);
    __half* out = agg + (size_t)node * d + lane * 4;
#pragma unroll 2
    for (int v = 0; v < nv; v++) {
        half2 h0 = __floats2half2_rn(acc[v].x * sc, acc[v].y * sc);
        half2 h1 = __floats2half2_rn(acc[v].z * sc, acc[v].w * sc);
        *(half2*)(out + v * 128) = h0;
        *(half2*)(out + v * 128 + 2) = h1;
    }
}

// ---------------- gather-mean layers 2/3: fp16 in/out, 2-edge unroll ------------
__global__ void gather_f16(int xoff, int d) {
    const __half* x = (const __half*)(g_scratch + xoff);
    __half* agg = (__half*)(g_scratch + OFF_AGG);
    const int* rp = (const int*)(g_scratch + OFF_RP);
    const int* csr = (const int*)(g_scratch + OFF_CSR);
    int node = (blockIdx.x * blockDim.x + threadIdx.x) >> 5;
    int lane = threadIdx.x & 31;
    if (node >= NN) return;
    int beg = rp[node], end = rp[node + 1];
    const int nv = d >> 8;

    float2 acc[8];
#pragma unroll
    for (int v = 0; v < 8; v++) acc[v] = make_float2(0.f, 0.f);

    int e = beg;
    for (; e + 1 < end; e += 2) {
        const __half* x0 = x + (size_t)csr[e] * d;
        const __half* x1 = x + (size_t)csr[e + 1] * d;
#pragma unroll 2
        for (int v = 0; v < nv; v++) {
            uint4 ra = *(const uint4*)(x0 + lane * 8 + v * 256);
            uint4 rb = *(const uint4*)(x1 + lane * 8 + v * 256);
            float2 a0 = __half22float2(*(half2*)&ra.x), b0 = __half22float2(*(half2*)&rb.x);
            float2 a1 = __half22float2(*(half2*)&ra.y), b1 = __half22float2(*(half2*)&rb.y);
            float2 a2 = __half22float2(*(half2*)&ra.z), b2 = __half22float2(*(half2*)&rb.z);
            float2 a3 = __half22float2(*(half2*)&ra.w), b3 = __half22float2(*(half2*)&rb.w);
            acc[v*4+0].x += a0.x + b0.x; acc[v*4+0].y += a0.y + b0.y;
            acc[v*4+1].x += a1.x + b1.x; acc[v*4+1].y += a1.y + b1.y;
            acc[v*4+2].x += a2.x + b2.x; acc[v*4+2].y += a2.y + b2.y;
            acc[v*4+3].x += a3.x + b3.x; acc[v*4+3].y += a3.y + b3.y;
        }
    }
    if (e < end) {
        const __half* x0 = x + (size_t)csr[e] * d;
#pragma unroll 2
        for (int v = 0; v < nv; v++) {
            uint4 ra = *(const uint4*)(x0 + lane * 8 + v * 256);
            float2 a0 = __half22float2(*(half2*)&ra.x);
            float2 a1 = __half22float2(*(half2*)&ra.y);
            float2 a2 = __half22float2(*(half2*)&ra.z);
            float2 a3 = __half22float2(*(half2*)&ra.w);
            acc[v*4+0].x += a0.x; acc[v*4+0].y += a0.y;
            acc[v*4+1].x += a1.x; acc[v*4+1].y += a1.y;
            acc[v*4+2].x += a2.x; acc[v*4+2].y += a2.y;
            acc[v*4+3].x += a3.x; acc[v*4+3].y += a3.y;
        }
    }
    float sc = 1.0f / (float)max(end - beg, 1);
    __half* out = agg + (size_t)node * d + lane * 8;
#pragma unroll 2
    for (int v = 0; v < nv; v++) {
        uint4 w;
        half2 h0 = __floats2half2_rn(acc[v*4+0].x * sc, acc[v*4+0].y * sc);
        half2 h1 = __floats2half2_rn(acc[v*4+1].x * sc, acc[v*4+1].y * sc);
        half2 h2 = __floats2half2_rn(acc[v*4+2].x * sc, acc[v*4+2].y * sc);
        half2 h3 = __floats2half2_rn(acc[v*4+3].x * sc, acc[v*4+3].y * sc);
        w.x = *(uint32_t*)&h0; w.y = *(uint32_t*)&h1;
        w.z = *(uint32_t*)&h2; w.w = *(uint32_t*)&h3;
        *(uint4*)(out + v * 256) = w;
    }
}

// ---------------- merged weight transpose -> fp16 -------------------------------
__global__ void transall_kernel(const float* __restrict__ W1l, const float* __restrict__ W1r,
                                const float* __restrict__ W2l, const float* __restrict__ W2r,
                                const float* __restrict__ W3l, const float* __restrict__ W3r,
                                const float* __restrict__ Wfc) {
    __shared__ float t[32][33];
    int b = blockIdx.x;
    const float* src; int dstOff, K, N, lt;
    if      (b < 128)  { src = W1l; dstOff = OFF_W1L; K = 256;  N = 512;  lt = b; }
    else if (b < 256)  { src = W1r; dstOff = OFF_W1R; K = 256;  N = 512;  lt = b - 128; }
    else if (b < 512)  { src = W2l; dstOff = OFF_W2L; K = 512;  N = 512;  lt = b - 256; }
    else if (b < 768)  { src = W2r; dstOff = OFF_W2R; K = 512;  N = 512;  lt = b - 512; }
    else if (b < 1280) { src = W3l; dstOff = OFF_W3L; K = 512;  N = 1024; lt = b - 768; }
    else if (b < 1792) { src = W3r; dstOff = OFF_W3R; K = 512;  N = 1024; lt = b - 1280; }
    else               { src = Wfc; dstOff = OFF_WFC; K = 1024; N = 512;  lt = b - 1792; }
    int ntx = N >> 5;
    int nb = (lt % ntx) * 32, kb = (lt / ntx) * 32;
    int tx = threadIdx.x, ty = threadIdx.y;
    for (int i = ty; i < 32; i += 8)
        t[i][tx] = src[(size_t)(kb + i) * N + nb + tx];
    __syncthreads();
    __half* dst = (__half*)(g_scratch + dstOff);
    for (int i = ty; i < 32; i += 8)
        dst[(size_t)(nb + i) * K + kb + tx] = __float2half_rn(t[tx][i]);
}

// ---------------- fp16 copy of x -------------------------------------------------
__global__ void cvt_kernel(const float* __restrict__ src, int n4) {
    __half* dst = (__half*)(g_scratch + OFF_XC);
    int i = blockIdx.x * blockDim.x + threadIdx.x;
    int stride = gridDim.x * blockDim.x;
    for (; i < n4; i += stride) {
        float4 v = ((const float4*)src)[i];
        half2 h0 = __floats2half2_rn(v.x, v.y);
        half2 h1 = __floats2half2_rn(v.z, v.w);
        uint2 w; w.x = *(uint32_t*)&h0; w.y = *(uint32_t*)&h1;
        *(uint2*)(dst + i * 4) = w;
    }
}

// ---------------- fp16 mma.sync GEMM, 4-stage cp.async + ldmatrix ---------------
#define BM 128
#define BN 128
#define BKC 32
#define PADH 40
#define NSTG 4
#define STG_H (BM * PADH)
#define SMEM_GEMM (NSTG * STG_H * 2 * 2)

__global__ __launch_bounds__(256, 2)
void gemm_mma(int a1off, int a2off, int hasA2,
              int b1off, int b2off, const float* __restrict__ bias,
              int coff, float* cext, int M, int N, int K, int doRelu, int outHalf) {
    extern __shared__ __half smh[];
    __half* sA = smh;
    __half* sB = smh + NSTG * STG_H;

    const __half* A1 = (const __half*)(g_scratch + a1off);
    const __half* A2 = (const __half*)(g_scratch + a2off);
    const __half* B1 = (const __half*)(g_scratch + b1off);
    const __half* B2 = (const __half*)(g_scratch + b2off);
    float* Cf = (coff >= 0) ? (g_scratch + coff) : cext;
    __half* Ch = (__half*)Cf;

    const int tid = threadIdx.x, wid = tid >> 5, lane = tid & 31;
    const int rowBase = blockIdx.y * BM;
    const int colBase = blockIdx.x * BN;
    const int wm = (wid >> 2) * 64;
    const int wn = (wid & 3) * 32;
    const int lr = tid >> 2;
    const int lc8 = (tid & 3) * 8;
    const int qrow = lane >> 2;
    const int qcol = lane & 3;

    const uint32_t sAu = smem_u32(sA);
    const uint32_t sBu = smem_u32(sB);

    // ldmatrix lane-address components (constant per thread)
    const int aRow = wm + (lane & 15);                 // + mi*16
    const int aColSel = (lane & 16) ? 8 : 0;           // + kof
    const int bRow = wn + (lane & 7) + ((lane & 16) ? 8 : 0);  // + j*16
    const int bColSel = (lane & 8) ? 8 : 0;            // + kof

    float acc[4][4][4];
#pragma unroll
    for (int mi = 0; mi < 4; mi++)
#pragma unroll
        for (int ni = 0; ni < 4; ni++)
#pragma unroll
            for (int r = 0; r < 4; r++) acc[mi][ni][r] = 0.f;

    const int Ktot = hasA2 ? 2 * K : K;
    const int nch = Ktot / BKC;

    auto load_stage = [&](int c) {
        int stg = c & (NSTG - 1);
        int k0 = c * BKC;
        const __half* A; const __half* B; int kk;
        if (k0 < K) { A = A1; B = B1; kk = k0; }
        else        { A = A2; B = B2; kk = k0 - K; }
#pragma unroll
        for (int p = 0; p < 2; p++) {
            int row = lr + p * 64;
            int gm = rowBase + row;
            const __half* src = A + (size_t)gm * K + kk + lc8;
            uint32_t dst = sAu + (uint32_t)(stg * STG_H + row * PADH + lc8) * 2u;
            uint32_t sz = (gm < M) ? 16u : 0u;
            asm volatile("cp.async.cg.shared.global [%0], [%1], 16, %2;"
                         :: "r"(dst), "l"(src), "r"(sz));
        }
#pragma unroll
        for (int p = 0; p < 2; p++) {
            int row = lr + p * 64;
            const __half* src = B + (size_t)(colBase + row) * K + kk + lc8;
            uint32_t dst = sBu + (uint32_t)(stg * STG_H + row * PADH + lc8) * 2u;
            asm volatile("cp.async.cg.shared.global [%0], [%1], 16, %2;"
                         :: "r"(dst), "l"(src), "r"(16u));
        }
    };

#pragma unroll
    for (int i = 0; i < NSTG - 1; i++) {
        if (i < nch) load_stage(i);
        asm volatile("cp.async.commit_group;" ::: "memory");
    }

    for (int ch = 0; ch < nch; ch++) {
        asm volatile("cp.async.wait_group 2;" ::: "memory");
        __syncthreads();

        int pre = ch + NSTG - 1;
        if (pre < nch) load_stage(pre);
        asm volatile("cp.async.commit_group;" ::: "memory");

        const uint32_t stA = sAu + (uint32_t)((ch & (NSTG - 1)) * STG_H) * 2u;
        const uint32_t stB = sBu + (uint32_t)((ch & (NSTG - 1)) * STG_H) * 2u;
#pragma unroll
        for (int ks = 0; ks < 2; ks++) {
            const int kof = ks * 16;
            uint32_t af[4][4], bf[4][2];
#pragma unroll
            for (int mi = 0; mi < 4; mi++) {
                uint32_t addr = stA + (uint32_t)((aRow + mi * 16) * PADH + kof + aColSel) * 2u;
                asm volatile("ldmatrix.sync.aligned.m8n8.x4.shared.b16 {%0,%1,%2,%3}, [%4];"
                             : "=r"(af[mi][0]), "=r"(af[mi][1]),
                               "=r"(af[mi][2]), "=r"(af[mi][3]) : "r"(addr));
            }
#pragma unroll
            for (int j = 0; j < 2; j++) {
                uint32_t addr = stB + (uint32_t)((bRow + j * 16) * PADH + kof + bColSel) * 2u;
                asm volatile("ldmatrix.sync.aligned.m8n8.x4.shared.b16 {%0,%1,%2,%3}, [%4];"
                             : "=r"(bf[2*j][0]), "=r"(bf[2*j][1]),
                               "=r"(bf[2*j+1][0]), "=r"(bf[2*j+1][1]) : "r"(addr));
            }
#pragma unroll
            for (int mi = 0; mi < 4; mi++)
#pragma unroll
                for (int ni = 0; ni < 4; ni++) {
                    asm volatile(
                        "mma.sync.aligned.m16n8k16.row.col.f32.f16.f16.f32 "
                        "{%0,%1,%2,%3}, {%4,%5,%6,%7}, {%8,%9}, {%0,%1,%2,%3};"
                        : "+f"(acc[mi][ni][0]), "+f"(acc[mi][ni][1]),
                          "+f"(acc[mi][ni][2]), "+f"(acc[mi][ni][3])
                        : "r"(af[mi][0]), "r"(af[mi][1]), "r"(af[mi][2]), "r"(af[mi][3]),
                          "r"(bf[ni][0]), "r"(bf[ni][1]));
                }
        }
    }

#pragma unroll
    for (int mi = 0; mi < 4; mi++) {
        int gm0 = rowBase + wm + mi * 16 + qrow;
        int gm1 = gm0 + 8;
#pragma unroll
        for (int ni = 0; ni < 4; ni++) {
            int col = colBase + wn + ni * 8 + 2 * qcol;
            float2 bv = *(const float2*)(bias + col);
            float r0 = acc[mi][ni][0] + bv.x;
            float r1 = acc[mi][ni][1] + bv.y;
            float r2 = acc[mi][ni][2] + bv.x;
            float r3 = acc[mi][ni][3] + bv.y;
            if (doRelu) {
                r0 = fmaxf(r0, 0.f); r1 = fmaxf(r1, 0.f);
                r2 = fmaxf(r2, 0.f); r3 = fmaxf(r3, 0.f);
            }
            if (outHalf) {
                half2 h0 = __floats2half2_rn(r0, r1);
                half2 h1 = __floats2half2_rn(r2, r3);
                if (gm0 < M) *(half2*)(Ch + (size_t)gm0 * N + col) = h0;
                if (gm1 < M) *(half2*)(Ch + (size_t)gm1 * N + col) = h1;
            } else {
                if (gm0 < M) *(float2*)(Cf + (size_t)gm0 * N + col) = make_float2(r0, r1);
                if (gm1 < M) *(float2*)(Cf + (size_t)gm1 * N + col) = make_float2(r2, r3);
            }
        }
    }
}

// ---------------- launch --------------------------------------------------------
extern "C" void kernel_launch(void* const* d_in, const int* in_sizes, int n_in,
                              void* d_out, int out_size) {
    const float* x   = (const float*)d_in[0];
    const int*   ei  = (const int*)d_in[1];
    const float* Wl1 = (const float*)d_in[2];
    const float* bl1 = (const float*)d_in[3];
    const float* Wr1 = (const float*)d_in[4];
    const float* Wl2 = (const float*)d_in[5];
    const float* bl2 = (const float*)d_in[6];
    const float* Wr2 = (const float*)d_in[7];
    const float* Wl3 = (const float*)d_in[8];
    const float* bl3 = (const float*)d_in[9];
    const float* Wr3 = (const float*)d_in[10];
    const float* Wfc = (const float*)d_in[11];
    const float* bfc = (const float*)d_in[12];
    float* out = (float*)d_out;

    cudaFuncSetAttribute(gemm_mma, cudaFuncAttributeMaxDynamicSharedMemorySize, SMEM_GEMM);

    const int M = NN, E = NE;
    dim3 tb(32, 8);

    transall_kernel<<<2304, tb>>>(Wl1, Wr1, Wl2, Wr2, Wl3, Wr3, Wfc);
    cvt_kernel<<<1250, 256>>>(x, NN * 256 / 4);

    zero2_kernel<<<40, 256>>>(OFF_CNT, SZ_CNT / 4, OFF_FILL, 20480 / 4);
    count_kernel<<<1250, 256>>>(ei, E);
    prefix_kernel<<<1, 1024>>>();
    fillcsr_kernel<<<1250, 256>>>(ei, E);

    const int gatherBlocks = (NN * 32 + 255) / 256;
    const int gy = (M + BM - 1) / BM;   // 157

    // ---- layer 1: 256 -> 512
    gather_f32<<<gatherBlocks, 256>>>(x, 256);
    gemm_mma<<<dim3(512 / BN, gy), 256, SMEM_GEMM>>>(
        OFF_AGG, OFF_XC, 1, OFF_W1L, OFF_W1R, bl1,
        OFF_H1, nullptr, M, 512, 256, 1, 1);

    // ---- layer 2: 512 -> 512
    gather_f16<<<gatherBlocks, 256>>>(OFF_H1, 512);
    gemm_mma<<<dim3(512 / BN, gy), 256, SMEM_GEMM>>>(
        OFF_AGG, OFF_H1, 1, OFF_W2L, OFF_W2R, bl2,
        OFF_H2, nullptr, M, 512, 512, 1, 1);

    // ---- layer 3: 512 -> 1024
    gather_f16<<<gatherBlocks, 256>>>(OFF_H2, 512);
    gemm_mma<<<dim3(1024 / BN, gy), 256, SMEM_GEMM>>>(
        OFF_AGG, OFF_H2, 1, OFF_W3L, OFF_W3R, bl3,
        OFF_H3, nullptr, M, 1024, 512, 1, 1);

    // ---- final FC: 1024 -> 512 (fp32 out)
    gemm_mma<<<dim3(512 / BN, gy), 256, SMEM_GEMM>>>(
        OFF_H3, OFF_H3, 0, OFF_WFC, OFF_WFC, bfc,
        -1, out, M, 512, 1024, 0, 0);
}

// round 15
// speedup vs baseline: 1.9266x; 1.0416x over previous
#include <cuda_runtime.h>
#include <cuda_fp16.h>
#include <cstdint>

#define NN 20000
#define NE 320000

// ---------------- single aligned device scratch (float-unit offsets) ----------
#define OFF_CNT 0
#define SZ_CNT  20480
#define OFF_AGG (OFF_CNT + SZ_CNT)
#define SZ_AGG  (NN * 512)
#define OFF_H1  (OFF_AGG + SZ_AGG)
#define SZ_H1   (NN * 512)
#define OFF_H2  (OFF_H1 + SZ_H1)
#define SZ_H2   (NN * 512)
#define OFF_H3  (OFF_H2 + SZ_H2)
#define SZ_H3   (NN * 1024)
#define OFF_W1L (OFF_H3 + SZ_H3)
#define OFF_W1R (OFF_W1L + 512*256)
#define OFF_W2L (OFF_W1R + 512*256)
#define OFF_W2R (OFF_W2L + 512*512)
#define OFF_W3L (OFF_W2R + 512*512)
#define OFF_W3R (OFF_W3L + 1024*512)
#define OFF_WFC (OFF_W3R + 1024*512)
#define OFF_XC  (OFF_WFC + 512*1024)
#define OFF_RP   (OFF_XC + NN*256)
#define OFF_FILL (OFF_RP + 20512)
#define OFF_CSR  (OFF_FILL + 20480)
#define SZ_TOTAL (OFF_CSR + NE)

__device__ __align__(128) float g_scratch[SZ_TOTAL];

__device__ __forceinline__ uint32_t smem_u32(const void* p) {
    uint32_t a;
    asm("{ .reg .u64 t; cvta.to.shared.u64 t, %1; cvt.u32.u64 %0, t; }" : "=r"(a) : "l"(p));
    return a;
}

// ---------------- merged prep: weight transposes + x->fp16 + zero ---------------
// blocks [0,2304): transall; [2304,2624): cvt x; [2624,2664): zero cnt+fill
__global__ void prep_kernel(const float* __restrict__ W1l, const float* __restrict__ W1r,
                            const float* __restrict__ W2l, const float* __restrict__ W2r,
                            const float* __restrict__ W3l, const float* __restrict__ W3r,
                            const float* __restrict__ Wfc, const float* __restrict__ x) {
    int b = blockIdx.x;
    int tid = threadIdx.y * 32 + threadIdx.x;   // block (32,8) = 256
    if (b >= 2624) {
        // zero cnt + fill (40960 ints = 10240 int4 over 40 blocks)
        int i = (b - 2624) * 256 + tid;
        int4 z = make_int4(0, 0, 0, 0);
        if (i < SZ_CNT / 4) ((int4*)(g_scratch + OFF_CNT))[i] = z;
        if (i < 20480 / 4) ((int4*)(g_scratch + OFF_FILL))[i] = z;
        return;
    }
    if (b >= 2304) {
        // cvt x -> fp16 (NN*256 floats = 1,280,000 float4 over 320 blocks)
        __half* dst = (__half*)(g_scratch + OFF_XC);
        int i = (b - 2304) * 256 + tid;
        int stride = 320 * 256;
        int n4 = NN * 256 / 4;
        for (; i < n4; i += stride) {
            float4 v = ((const float4*)x)[i];
            half2 h0 = __floats2half2_rn(v.x, v.y);
            half2 h1 = __floats2half2_rn(v.z, v.w);
            uint2 w; w.x = *(uint32_t*)&h0; w.y = *(uint32_t*)&h1;
            *(uint2*)(dst + i * 4) = w;
        }
        return;
    }
    __shared__ float t[32][33];
    const float* src; int dstOff, K, N, lt;
    if      (b < 128)  { src = W1l; dstOff = OFF_W1L; K = 256;  N = 512;  lt = b; }
    else if (b < 256)  { src = W1r; dstOff = OFF_W1R; K = 256;  N = 512;  lt = b - 128; }
    else if (b < 512)  { src = W2l; dstOff = OFF_W2L; K = 512;  N = 512;  lt = b - 256; }
    else if (b < 768)  { src = W2r; dstOff = OFF_W2R; K = 512;  N = 512;  lt = b - 512; }
    else if (b < 1280) { src = W3l; dstOff = OFF_W3L; K = 512;  N = 1024; lt = b - 768; }
    else if (b < 1792) { src = W3r; dstOff = OFF_W3R; K = 512;  N = 1024; lt = b - 1280; }
    else               { src = Wfc; dstOff = OFF_WFC; K = 1024; N = 512;  lt = b - 1792; }
    int ntx = N >> 5;
    int nb = (lt % ntx) * 32, kb = (lt / ntx) * 32;
    int tx = threadIdx.x, ty = threadIdx.y;
    for (int i = ty; i < 32; i += 8)
        t[i][tx] = src[(size_t)(kb + i) * N + nb + tx];
    __syncthreads();
    __half* dst = (__half*)(g_scratch + dstOff);
    for (int i = ty; i < 32; i += 8)
        dst[(size_t)(nb + i) * K + kb + tx] = __float2half_rn(t[tx][i]);
}

// ---------------- degree count (int) -------------------------------------------
__global__ void count_kernel(const int* __restrict__ ei, int E) {
    int* cnt = (int*)(g_scratch + OFF_CNT);
    int i = blockIdx.x * blockDim.x + threadIdx.x;
    int stride = gridDim.x * blockDim.x;
    for (; i < E; i += stride) atomicAdd(&cnt[ei[E + i]], 1);
}

// ---------------- prefix sum (chunked, warp-shfl block scan) --------------------
#define PCH 20
__global__ void prefix_kernel() {
    const int tid = threadIdx.x;
    int* rp = (int*)(g_scratch + OFF_RP);
    const int* cnt = (const int*)(g_scratch + OFF_CNT);
    int beg = tid * PCH;
    int local[PCH];
    int s = 0;
#pragma unroll
    for (int j = 0; j < PCH; j++) {
        int i = beg + j;
        int v = (i < NN) ? cnt[i] : 0;
        local[j] = v; s += v;
    }
    int lane = tid & 31, wid = tid >> 5;
    int sc = s;
#pragma unroll
    for (int o = 1; o < 32; o <<= 1) {
        int t = __shfl_up_sync(~0u, sc, o);
        if (lane >= o) sc += t;
    }
    __shared__ int wsum[32];
    if (lane == 31) wsum[wid] = sc;
    __syncthreads();
    if (wid == 0) {
        int w = wsum[lane];
#pragma unroll
        for (int o = 1; o < 32; o <<= 1) {
            int t = __shfl_up_sync(~0u, w, o);
            if (lane >= o) w += t;
        }
        wsum[lane] = w;
    }
    __syncthreads();
    int run = sc - s + ((wid > 0) ? wsum[wid - 1] : 0);
    if (tid == 0) rp[0] = 0;
#pragma unroll
    for (int j = 0; j < PCH; j++) {
        int i = beg + j;
        if (i < NN) { run += local[j]; rp[i + 1] = run; }
    }
}

// ---------------- fill CSR ------------------------------------------------------
__global__ void fillcsr_kernel(const int* __restrict__ ei, int E) {
    const int* rp = (const int*)(g_scratch + OFF_RP);
    int* fill = (int*)(g_scratch + OFF_FILL);
    int* csr = (int*)(g_scratch + OFF_CSR);
    int i = blockIdx.x * blockDim.x + threadIdx.x;
    int stride = gridDim.x * blockDim.x;
    for (; i < E; i += stride) {
        int s = ei[i];
        int t = ei[E + i];
        int pos = rp[t] + atomicAdd(&fill[t], 1);
        csr[pos] = s;
    }
}

// ---------------- gather-mean: fp16 in/out, 4-edge unroll -----------------------
// d in halves (256 or 512); nv = d/256 uint4 per lane
__global__ void gather_f16(int xoff, int d) {
    const __half* x = (const __half*)(g_scratch + xoff);
    __half* agg = (__half*)(g_scratch + OFF_AGG);
    const int* rp = (const int*)(g_scratch + OFF_RP);
    const int* csr = (const int*)(g_scratch + OFF_CSR);
    int node = (blockIdx.x * blockDim.x + threadIdx.x) >> 5;
    int lane = threadIdx.x & 31;
    if (node >= NN) return;
    int beg = rp[node], end = rp[node + 1];
    const int nv = d >> 8;

    float2 acc[8];
#pragma unroll
    for (int v = 0; v < 8; v++) acc[v] = make_float2(0.f, 0.f);

    int e = beg;
    for (; e + 3 < end; e += 4) {
        const __half* x0 = x + (size_t)csr[e] * d;
        const __half* x1 = x + (size_t)csr[e + 1] * d;
        const __half* x2 = x + (size_t)csr[e + 2] * d;
        const __half* x3 = x + (size_t)csr[e + 3] * d;
#pragma unroll 2
        for (int v = 0; v < nv; v++) {
            uint4 ra = *(const uint4*)(x0 + lane * 8 + v * 256);
            uint4 rb = *(const uint4*)(x1 + lane * 8 + v * 256);
            uint4 rc = *(const uint4*)(x2 + lane * 8 + v * 256);
            uint4 rd = *(const uint4*)(x3 + lane * 8 + v * 256);
#pragma unroll
            for (int q = 0; q < 4; q++) {
                uint32_t wa = (&ra.x)[q], wb = (&rb.x)[q], wc = (&rc.x)[q], wd = (&rd.x)[q];
                float2 fa = __half22float2(*(half2*)&wa);
                float2 fb = __half22float2(*(half2*)&wb);
                float2 fc = __half22float2(*(half2*)&wc);
                float2 fd = __half22float2(*(half2*)&wd);
                acc[v*4+q].x += (fa.x + fb.x) + (fc.x + fd.x);
                acc[v*4+q].y += (fa.y + fb.y) + (fc.y + fd.y);
            }
        }
    }
    for (; e < end; e++) {
        const __half* x0 = x + (size_t)csr[e] * d;
#pragma unroll 2
        for (int v = 0; v < nv; v++) {
            uint4 ra = *(const uint4*)(x0 + lane * 8 + v * 256);
#pragma unroll
            for (int q = 0; q < 4; q++) {
                uint32_t wa = (&ra.x)[q];
                float2 fa = __half22float2(*(half2*)&wa);
                acc[v*4+q].x += fa.x;
                acc[v*4+q].y += fa.y;
            }
        }
    }
    float sc = 1.0f / (float)max(end - beg, 1);
    __half* out = agg + (size_t)node * d + lane * 8;
#pragma unroll 2
    for (int v = 0; v < nv; v++) {
        uint4 w;
#pragma unroll
        for (int q = 0; q < 4; q++) {
            half2 h = __floats2half2_rn(acc[v*4+q].x * sc, acc[v*4+q].y * sc);
            (&w.x)[q] = *(uint32_t*)&h;
        }
        *(uint4*)(out + v * 256) = w;
    }
}

// ---------------- fp16 mma.sync GEMM, 4-stage cp.async + ldmatrix ---------------
#define BM 128
#define BN 128
#define BKC 32
#define PADH 40
#define NSTG 4
#define STG_H (BM * PADH)
#define SMEM_GEMM (NSTG * STG_H * 2 * 2)

__global__ __launch_bounds__(256, 2)
void gemm_mma(int a1off, int a2off, int hasA2,
              int b1off, int b2off, const float* __restrict__ bias,
              int coff, float* cext, int M, int N, int K, int doRelu, int outHalf) {
    extern __shared__ __half smh[];
    __half* sA = smh;
    __half* sB = smh + NSTG * STG_H;

    const __half* A1 = (const __half*)(g_scratch + a1off);
    const __half* A2 = (const __half*)(g_scratch + a2off);
    const __half* B1 = (const __half*)(g_scratch + b1off);
    const __half* B2 = (const __half*)(g_scratch + b2off);
    float* Cf = (coff >= 0) ? (g_scratch + coff) : cext;
    __half* Ch = (__half*)Cf;

    const int tid = threadIdx.x, wid = tid >> 5, lane = tid & 31;
    const int rowBase = blockIdx.y * BM;
    const int colBase = blockIdx.x * BN;
    const int wm = (wid >> 2) * 64;
    const int wn = (wid & 3) * 32;
    const int lr = tid >> 2;
    const int lc8 = (tid & 3) * 8;
    const int qrow = lane >> 2;
    const int qcol = lane & 3;

    const uint32_t sAu = smem_u32(sA);
    const uint32_t sBu = smem_u32(sB);

    const int aRow = wm + (lane & 15);
    const int aColSel = (lane & 16) ? 8 : 0;
    const int bRow = wn + (lane & 7) + ((lane & 16) ? 8 : 0);
    const int bColSel = (lane & 8) ? 8 : 0;

    float acc[4][4][4];
#pragma unroll
    for (int mi = 0; mi < 4; mi++)
#pragma unroll
        for (int ni = 0; ni < 4; ni++)
#pragma unroll
            for (int r = 0; r < 4; r++) acc[mi][ni][r] = 0.f;

    const int Ktot = hasA2 ? 2 * K : K;
    const int nch = Ktot / BKC;

    auto load_stage = [&](int c) {
        int stg = c & (NSTG - 1);
        int k0 = c * BKC;
        const __half* A; const __half* B; int kk;
        if (k0 < K) { A = A1; B = B1; kk = k0; }
        else        { A = A2; B = B2; kk = k0 - K; }
#pragma unroll
        for (int p = 0; p < 2; p++) {
            int row = lr + p * 64;
            int gm = rowBase + row;
            const __half* src = A + (size_t)gm * K + kk + lc8;
            uint32_t dst = sAu + (uint32_t)(stg * STG_H + row * PADH + lc8) * 2u;
            uint32_t sz = (gm < M) ? 16u : 0u;
            asm volatile("cp.async.cg.shared.global [%0], [%1], 16, %2;"
                         :: "r"(dst), "l"(src), "r"(sz));
        }
#pragma unroll
        for (int p = 0; p < 2; p++) {
            int row = lr + p * 64;
            const __half* src = B + (size_t)(colBase + row) * K + kk + lc8;
            uint32_t dst = sBu + (uint32_t)(stg * STG_H + row * PADH + lc8) * 2u;
            asm volatile("cp.async.cg.shared.global [%0], [%1], 16, %2;"
                         :: "r"(dst), "l"(src), "r"(16u));
        }
    };

#pragma unroll
    for (int i = 0; i < NSTG - 1; i++) {
        if (i < nch) load_stage(i);
        asm volatile("cp.async.commit_group;" ::: "memory");
    }

    for (int ch = 0; ch < nch; ch++) {
        asm volatile("cp.async.wait_group 2;" ::: "memory");
        __syncthreads();

        int pre = ch + NSTG - 1;
        if (pre < nch) load_stage(pre);
        asm volatile("cp.async.commit_group;" ::: "memory");

        const uint32_t stA = sAu + (uint32_t)((ch & (NSTG - 1)) * STG_H) * 2u;
        const uint32_t stB = sBu + (uint32_t)((ch & (NSTG - 1)) * STG_H) * 2u;
#pragma unroll
        for (int ks = 0; ks < 2; ks++) {
            const int kof = ks * 16;
            uint32_t af[4][4], bf[4][2];
#pragma unroll
            for (int mi = 0; mi < 4; mi++) {
                uint32_t addr = stA + (uint32_t)((aRow + mi * 16) * PADH + kof + aColSel) * 2u;
                asm volatile("ldmatrix.sync.aligned.m8n8.x4.shared.b16 {%0,%1,%2,%3}, [%4];"
                             : "=r"(af[mi][0]), "=r"(af[mi][1]),
                               "=r"(af[mi][2]), "=r"(af[mi][3]) : "r"(addr));
            }
#pragma unroll
            for (int j = 0; j < 2; j++) {
                uint32_t addr = stB + (uint32_t)((bRow + j * 16) * PADH + kof + bColSel) * 2u;
                asm volatile("ldmatrix.sync.aligned.m8n8.x4.shared.b16 {%0,%1,%2,%3}, [%4];"
                             : "=r"(bf[2*j][0]), "=r"(bf[2*j][1]),
                               "=r"(bf[2*j+1][0]), "=r"(bf[2*j+1][1]) : "r"(addr));
            }
#pragma unroll
            for (int mi = 0; mi < 4; mi++)
#pragma unroll
                for (int ni = 0; ni < 4; ni++) {
                    asm volatile(
                        "mma.sync.aligned.m16n8k16.row.col.f32.f16.f16.f32 "
                        "{%0,%1,%2,%3}, {%4,%5,%6,%7}, {%8,%9}, {%0,%1,%2,%3};"
                        : "+f"(acc[mi][ni][0]), "+f"(acc[mi][ni][1]),
                          "+f"(acc[mi][ni][2]), "+f"(acc[mi][ni][3])
                        : "r"(af[mi][0]), "r"(af[mi][1]), "r"(af[mi][2]), "r"(af[mi][3]),
                          "r"(bf[ni][0]), "r"(bf[ni][1]));
                }
        }
    }

#pragma unroll
    for (int mi = 0; mi < 4; mi++) {
        int gm0 = rowBase + wm + mi * 16 + qrow;
        int gm1 = gm0 + 8;
#pragma unroll
        for (int ni = 0; ni < 4; ni++) {
            int col = colBase + wn + ni * 8 + 2 * qcol;
            float2 bv = *(const float2*)(bias + col);
            float r0 = acc[mi][ni][0] + bv.x;
            float r1 = acc[mi][ni][1] + bv.y;
            float r2 = acc[mi][ni][2] + bv.x;
            float r3 = acc[mi][ni][3] + bv.y;
            if (doRelu) {
                r0 = fmaxf(r0, 0.f); r1 = fmaxf(r1, 0.f);
                r2 = fmaxf(r2, 0.f); r3 = fmaxf(r3, 0.f);
            }
            if (outHalf) {
                half2 h0 = __floats2half2_rn(r0, r1);
                half2 h1 = __floats2half2_rn(r2, r3);
                if (gm0 < M) *(half2*)(Ch + (size_t)gm0 * N + col) = h0;
                if (gm1 < M) *(half2*)(Ch + (size_t)gm1 * N + col) = h1;
            } else {
                if (gm0 < M) *(float2*)(Cf + (size_t)gm0 * N + col) = make_float2(r0, r1);
                if (gm1 < M) *(float2*)(Cf + (size_t)gm1 * N + col) = make_float2(r2, r3);
            }
        }
    }
}

// ---------------- launch --------------------------------------------------------
extern "C" void kernel_launch(void* const* d_in, const int* in_sizes, int n_in,
                              void* d_out, int out_size) {
    const float* x   = (const float*)d_in[0];
    const int*   ei  = (const int*)d_in[1];
    const float* Wl1 = (const float*)d_in[2];
    const float* bl1 = (const float*)d_in[3];
    const float* Wr1 = (const float*)d_in[4];
    const float* Wl2 = (const float*)d_in[5];
    const float* bl2 = (const float*)d_in[6];
    const float* Wr2 = (const float*)d_in[7];
    const float* Wl3 = (const float*)d_in[8];
    const float* bl3 = (const float*)d_in[9];
    const float* Wr3 = (const float*)d_in[10];
    const float* Wfc = (const float*)d_in[11];
    const float* bfc = (const float*)d_in[12];
    float* out = (float*)d_out;

    cudaFuncSetAttribute(gemm_mma, cudaFuncAttributeMaxDynamicSharedMemorySize, SMEM_GEMM);

    const int M = NN, E = NE;
    dim3 tb(32, 8);

    // merged prep: transposes + x->fp16 + zero(cnt/fill)
    prep_kernel<<<2664, tb>>>(Wl1, Wr1, Wl2, Wr2, Wl3, Wr3, Wfc, x);
    count_kernel<<<1250, 256>>>(ei, E);
    prefix_kernel<<<1, 1024>>>();
    fillcsr_kernel<<<1250, 256>>>(ei, E);

    const int gatherBlocks = (NN * 32 + 255) / 256;
    const int gy = (M + BM - 1) / BM;   // 157

    // ---- layer 1: 256 -> 512 (gather from fp16 x copy)
    gather_f16<<<gatherBlocks, 256>>>(OFF_XC, 256);
    gemm_mma<<<dim3(512 / BN, gy), 256, SMEM_GEMM>>>(
        OFF_AGG, OFF_XC, 1, OFF_W1L, OFF_W1R, bl1,
        OFF_H1, nullptr, M, 512, 256, 1, 1);

    // ---- layer 2: 512 -> 512
    gather_f16<<<gatherBlocks, 256>>>(OFF_H1, 512);
    gemm_mma<<<dim3(512 / BN, gy), 256, SMEM_GEMM>>>(
        OFF_AGG, OFF_H1, 1, OFF_W2L, OFF_W2R, bl2,
        OFF_H2, nullptr, M, 512, 512, 1, 1);

    // ---- layer 3: 512 -> 1024
    gather_f16<<<gatherBlocks, 256>>>(OFF_H2, 512);
    gemm_mma<<<dim3(1024 / BN, gy), 256, SMEM_GEMM>>>(
        OFF_AGG, OFF_H2, 1, OFF_W3L, OFF_W3R, bl3,
        OFF_H3, nullptr, M, 1024, 512, 1, 1);

    // ---- final FC: 1024 -> 512 (fp32 out)
    gemm_mma<<<dim3(512 / BN, gy), 256, SMEM_GEMM>>>(
        OFF_H3, OFF_H3, 0, OFF_WFC, OFF_WFC, bfc,
        -1, out, M, 512, 1024, 0, 0);
}